// round 1
// baseline (speedup 1.0000x reference)
#include <cuda_runtime.h>
#include <cstdint>
#include <cstdio>

// ---------------------------------------------------------------------------
// GAT 3-layer forward.  N=50000 nodes, E=800000 edges, hidden 2 heads x 64.
// Pipeline per layer:
//   1. gemm:   feat = in @ W^T                      [N, H*F]
//   2. zero:   agg=0, denom=0, M=enc(-inf)
//   3. score:  s[n,h] = leaky_relu(dot(feat[n,h,:], attn[h,:])); atomicMax M[h]
//   4. denom:  denom[dst,h] += exp(s[src,h]-M[h])       (per edge)
//   5. agg:    agg[dst,h,:] += exp(s[src,h]-M[h])/denom[dst,h] * feat[src,h,:]
//   6. epi:    out = relu(agg + bias)  (final layer: no relu)
// Global-max subtraction is exactly equivalent to per-dst max in the softmax
// ratio; it only differs in rounding, and keeps exp() in safe range.
// ---------------------------------------------------------------------------

#define MAXN 50000
#define MAXW 128

__device__ float g_feat[MAXN * MAXW];
__device__ float g_agg [MAXN * MAXW];
__device__ float g_hid [MAXN * MAXW];
__device__ float g_s   [MAXN * 2];
__device__ float g_den [MAXN * 2];
__device__ unsigned g_M[2];

__device__ __forceinline__ unsigned enc_f(float f) {
    unsigned u = __float_as_uint(f);
    return (u & 0x80000000u) ? ~u : (u | 0x80000000u);
}
__device__ __forceinline__ float dec_f(unsigned u) {
    return (u & 0x80000000u) ? __uint_as_float(u ^ 0x80000000u)
                             : __uint_as_float(~u);
}

// ---------------- GEMM: C[N][BN] = A[N][128] @ W[BN][128]^T ----------------
// Block tile 64 rows x BN cols, 256 threads, per-thread RT rows x 4 cols.
template <int BN>
__global__ void gemm_kernel(const float* __restrict__ A,
                            const float* __restrict__ W,
                            float* __restrict__ C, int N) {
    constexpr int BM = 64, K = 128;
    constexpr int CB = BN / 4;       // col-groups of 4
    constexpr int RB = 256 / CB;     // row-groups
    constexpr int RT = BM / RB;      // rows per thread
    extern __shared__ float sm[];
    float* As = sm;                  // [BM][K]
    float* Ws = sm + BM * K;         // [K][BN]  (transposed W)

    const int tid  = threadIdx.x;
    const int row0 = blockIdx.x * BM;

    // load A tile (float4, coalesced), zero-pad tail rows
    const float4* A4  = (const float4*)A;
    float4*       As4 = (float4*)As;
    for (int i = tid; i < BM * 32; i += 256) {
        int r = i >> 5, kk = i & 31;
        float4 v = make_float4(0.f, 0.f, 0.f, 0.f);
        if (row0 + r < N) v = A4[(size_t)(row0 + r) * 32 + kk];
        As4[i] = v;
    }
    // load W transposed into Ws[k][c]
    const float4* W4 = (const float4*)W;
    for (int i = tid; i < BN * 32; i += 256) {
        int c = i >> 5, kk = i & 31;
        float4 v = W4[(size_t)c * 32 + kk];
        Ws[(kk * 4 + 0) * BN + c] = v.x;
        Ws[(kk * 4 + 1) * BN + c] = v.y;
        Ws[(kk * 4 + 2) * BN + c] = v.z;
        Ws[(kk * 4 + 3) * BN + c] = v.w;
    }
    __syncthreads();

    const int cb = tid % CB;
    const int rb = tid / CB;
    const int rbase = rb * RT;
    const float4* Ws4 = (const float4*)Ws;

    float acc[RT][4];
#pragma unroll
    for (int r = 0; r < RT; r++) { acc[r][0] = acc[r][1] = acc[r][2] = acc[r][3] = 0.f; }

#pragma unroll 4
    for (int k4 = 0; k4 < 32; k4++) {
        float4 a4[RT];
#pragma unroll
        for (int r = 0; r < RT; r++) a4[r] = As4[(rbase + r) * 32 + k4];
#pragma unroll
        for (int j = 0; j < 4; j++) {
            float4 w = Ws4[(k4 * 4 + j) * CB + cb];
#pragma unroll
            for (int r = 0; r < RT; r++) {
                float av = (j == 0) ? a4[r].x : (j == 1) ? a4[r].y : (j == 2) ? a4[r].z : a4[r].w;
                acc[r][0] = fmaf(av, w.x, acc[r][0]);
                acc[r][1] = fmaf(av, w.y, acc[r][1]);
                acc[r][2] = fmaf(av, w.z, acc[r][2]);
                acc[r][3] = fmaf(av, w.w, acc[r][3]);
            }
        }
    }

    float4* C4 = (float4*)C;
#pragma unroll
    for (int r = 0; r < RT; r++) {
        int row = row0 + rbase + r;
        if (row < N)
            C4[(size_t)row * CB + cb] = make_float4(acc[r][0], acc[r][1], acc[r][2], acc[r][3]);
    }
}

// ---------------- zero scratch ----------------
__global__ void zero_kernel(float* __restrict__ agg, int nAgg,
                            float* __restrict__ den, int nDen,
                            unsigned* __restrict__ M, int nM) {
    int i = blockIdx.x * blockDim.x + threadIdx.x;
    if (i < nAgg) agg[i] = 0.f;
    if (i < nDen) den[i] = 0.f;
    if (i < nM)   M[i]   = 0u;   // < enc(any finite float)
}

// ---------------- per-node attention score + global max ----------------
template <int H, int F>
__global__ void score_kernel(const float* __restrict__ feat,
                             const float* __restrict__ attn,
                             float* __restrict__ s,
                             unsigned* __restrict__ M, int N) {
    constexpr int NV4 = H * F / 4;         // float4s per node (<=32)
    constexpr int LPH = F / 4;             // lanes per head
    int gid  = blockIdx.x * blockDim.x + threadIdx.x;
    int node = gid >> 5;
    int lane = gid & 31;
    if (node >= N) return;
    float p = 0.f;
    if (lane < NV4) {
        float4 f = ((const float4*)feat)[(size_t)node * NV4 + lane];
        float4 a = ((const float4*)attn)[lane];
        p = f.x * a.x + f.y * a.y + f.z * a.z + f.w * a.w;
    }
#pragma unroll
    for (int off = LPH / 2; off >= 1; off >>= 1)
        p += __shfl_xor_sync(0xffffffffu, p, off);
    if (lane < NV4 && (lane % LPH) == 0) {
        int h = lane / LPH;
        float sv = p > 0.f ? p : 0.2f * p;   // leaky relu
        s[(size_t)node * H + h] = sv;
        atomicMax(&M[h], enc_f(sv));
    }
}

// ---------------- softmax denominator ----------------
template <int H>
__global__ void denom_kernel(const int* __restrict__ src,
                             const int* __restrict__ dst,
                             const float* __restrict__ s,
                             const unsigned* __restrict__ M,
                             float* __restrict__ den, int E) {
    int e = blockIdx.x * blockDim.x + threadIdx.x;
    if (e >= E) return;
    int u = src[e], v = dst[e];
#pragma unroll
    for (int h = 0; h < H; h++) {
        float mv = dec_f(M[h]);
        atomicAdd(&den[(size_t)v * H + h], __expf(s[(size_t)u * H + h] - mv));
    }
}

// ---------------- weighted aggregation (warp per edge) ----------------
template <int H, int F>
__global__ void agg_kernel(const int* __restrict__ src,
                           const int* __restrict__ dst,
                           const float* __restrict__ feat,
                           const float* __restrict__ s,
                           const unsigned* __restrict__ M,
                           const float* __restrict__ den,
                           float* __restrict__ agg, int E) {
    constexpr int NV4 = H * F / 4;
    constexpr int LPH = F / 4;
    int gid  = blockIdx.x * blockDim.x + threadIdx.x;
    int e    = gid >> 5;
    int lane = gid & 31;
    if (e >= E || lane >= NV4) return;
    int u = __ldg(&src[e]);
    int v = __ldg(&dst[e]);
    int h = lane / LPH;
    float w = __expf(s[(size_t)u * H + h] - dec_f(M[h])) / den[(size_t)v * H + h];
    float4 f = ((const float4*)feat)[(size_t)u * NV4 + lane];
    float4* dstp = ((float4*)agg) + (size_t)v * NV4 + lane;
    float x = f.x * w, y = f.y * w, z = f.z * w, q = f.w * w;
    asm volatile("red.global.add.v4.f32 [%0], {%1,%2,%3,%4};"
                 :: "l"(dstp), "f"(x), "f"(y), "f"(z), "f"(q) : "memory");
}

// ---------------- epilogue: bias (+relu) ----------------
template <bool RELU>
__global__ void epi_kernel(const float* __restrict__ agg,
                           const float* __restrict__ bias,
                           float* __restrict__ out, int total, int width) {
    int i = blockIdx.x * blockDim.x + threadIdx.x;
    if (i >= total) return;
    float v = agg[i] + bias[i % width];
    if (RELU) v = v > 0.f ? v : 0.f;
    out[i] = v;
}

// ---------------------------------------------------------------------------
extern "C" void kernel_launch(void* const* d_in, const int* in_sizes, int n_in,
                              void* d_out, int out_size) {
    const float* feat    = (const float*)d_in[0];
    const float* W0      = (const float*)d_in[1];
    const float* attn_l0 = (const float*)d_in[2];
    const float* bias0   = (const float*)d_in[3];
    const float* W1      = (const float*)d_in[4];
    const float* attn_l1 = (const float*)d_in[5];
    const float* bias1   = (const float*)d_in[6];
    const float* W2      = (const float*)d_in[7];
    const float* attn_l2 = (const float*)d_in[8];
    const float* bias2   = (const float*)d_in[9];
    const int*   src     = (const int*)d_in[10];
    const int*   dst     = (const int*)d_in[11];

    const int N = in_sizes[0] / 128;
    const int E = in_sizes[10];

    float *p_feat, *p_agg, *p_hid, *p_s, *p_den;
    unsigned* p_M;
    cudaGetSymbolAddress((void**)&p_feat, g_feat);
    cudaGetSymbolAddress((void**)&p_agg,  g_agg);
    cudaGetSymbolAddress((void**)&p_hid,  g_hid);
    cudaGetSymbolAddress((void**)&p_s,    g_s);
    cudaGetSymbolAddress((void**)&p_den,  g_den);
    cudaGetSymbolAddress((void**)&p_M,    g_M);

    const int SM128 = (64 * 128 + 128 * 128) * 4;  // 96 KB
    const int SM64  = (64 * 128 + 128 * 64) * 4;   // 64 KB
    cudaFuncSetAttribute(gemm_kernel<128>, cudaFuncAttributeMaxDynamicSharedMemorySize, SM128);
    cudaFuncSetAttribute(gemm_kernel<64>,  cudaFuncAttributeMaxDynamicSharedMemorySize, SM64);

    const int gGemm  = (N + 63) / 64;
    const int gScore = (N * 32 + 255) / 256;
    const int gEdgeT = (E + 255) / 256;
    const int gEdgeW = (E * 32 + 255) / 256;

    // -------- layer 0 --------
    gemm_kernel<128><<<gGemm, 256, SM128>>>(feat, W0, p_feat, N);
    zero_kernel<<<(N * 128 + 255) / 256, 256>>>(p_agg, N * 128, p_den, N * 2, p_M, 2);
    score_kernel<2, 64><<<gScore, 256>>>(p_feat, attn_l0, p_s, p_M, N);
    denom_kernel<2><<<gEdgeT, 256>>>(src, dst, p_s, p_M, p_den, E);
    agg_kernel<2, 64><<<gEdgeW, 256>>>(src, dst, p_feat, p_s, p_M, p_den, p_agg, E);
    epi_kernel<true><<<(N * 128 + 255) / 256, 256>>>(p_agg, bias0, p_hid, N * 128, 128);

    // -------- layer 1 --------
    gemm_kernel<128><<<gGemm, 256, SM128>>>(p_hid, W1, p_feat, N);
    zero_kernel<<<(N * 128 + 255) / 256, 256>>>(p_agg, N * 128, p_den, N * 2, p_M, 2);
    score_kernel<2, 64><<<gScore, 256>>>(p_feat, attn_l1, p_s, p_M, N);
    denom_kernel<2><<<gEdgeT, 256>>>(src, dst, p_s, p_M, p_den, E);
    agg_kernel<2, 64><<<gEdgeW, 256>>>(src, dst, p_feat, p_s, p_M, p_den, p_agg, E);
    epi_kernel<true><<<(N * 128 + 255) / 256, 256>>>(p_agg, bias1, p_hid, N * 128, 128);

    // -------- layer 2 (single head, no relu, output) --------
    gemm_kernel<64><<<gGemm, 256, SM64>>>(p_hid, W2, p_feat, N);
    zero_kernel<<<(N * 64 + 255) / 256, 256>>>(p_agg, N * 64, p_den, N * 1, p_M, 1);
    score_kernel<1, 64><<<gScore, 256>>>(p_feat, attn_l2, p_s, p_M, N);
    denom_kernel<1><<<gEdgeT, 256>>>(src, dst, p_s, p_M, p_den, E);
    agg_kernel<1, 64><<<gEdgeW, 256>>>(src, dst, p_feat, p_s, p_M, p_den, p_agg, E);
    epi_kernel<false><<<(N * 64 + 255) / 256, 256>>>(p_agg, bias2, (float*)d_out, N * 64, 64);
}

// round 2
// speedup vs baseline: 1.3824x; 1.3824x over previous
#include <cuda_runtime.h>
#include <cstdint>

// ---------------------------------------------------------------------------
// GAT 3-layer forward, gather-based (CSR by dst), no float atomics.
// Per launch: build CSR once; per layer: gemm -> score -> exp -> node-gather.
// ---------------------------------------------------------------------------

#define MAXN 50000
#define MAXE 800000
#define MAXW 128

__device__ float g_feat[MAXN * MAXW];
__device__ float g_hid [MAXN * MAXW];
__device__ float g_s   [MAXN * 2];
__device__ float g_t   [MAXN * 2];
__device__ unsigned g_M[2];
__device__ int g_cnt[MAXN + 1];
__device__ int g_ptr[MAXN + 1];
__device__ int g_cur[MAXN + 1];
__device__ int g_csr[MAXE];

__device__ __forceinline__ unsigned enc_f(float f) {
    unsigned u = __float_as_uint(f);
    return (u & 0x80000000u) ? ~u : (u | 0x80000000u);
}
__device__ __forceinline__ float dec_f(unsigned u) {
    return (u & 0x80000000u) ? __uint_as_float(u ^ 0x80000000u)
                             : __uint_as_float(~u);
}

// ---------------- GEMM: C[N][BN] = A[N][128] @ W[BN][128]^T ----------------
template <int BN>
__global__ void gemm_kernel(const float* __restrict__ A,
                            const float* __restrict__ W,
                            float* __restrict__ C, int N) {
    constexpr int BM = 64, K = 128;
    constexpr int CB = BN / 4;
    constexpr int RB = 256 / CB;
    constexpr int RT = BM / RB;
    extern __shared__ float sm[];
    float* As = sm;                  // [BM][K]
    float* Ws = sm + BM * K;         // [K][BN]

    const int tid  = threadIdx.x;
    const int row0 = blockIdx.x * BM;

    const float4* A4  = (const float4*)A;
    float4*       As4 = (float4*)As;
    for (int i = tid; i < BM * 32; i += 256) {
        int r = i >> 5, kk = i & 31;
        float4 v = make_float4(0.f, 0.f, 0.f, 0.f);
        if (row0 + r < N) v = A4[(size_t)(row0 + r) * 32 + kk];
        As4[i] = v;
    }
    const float4* W4 = (const float4*)W;
    for (int i = tid; i < BN * 32; i += 256) {
        int c = i >> 5, kk = i & 31;
        float4 v = W4[(size_t)c * 32 + kk];
        Ws[(kk * 4 + 0) * BN + c] = v.x;
        Ws[(kk * 4 + 1) * BN + c] = v.y;
        Ws[(kk * 4 + 2) * BN + c] = v.z;
        Ws[(kk * 4 + 3) * BN + c] = v.w;
    }
    __syncthreads();

    const int cb = tid % CB;
    const int rb = tid / CB;
    const int rbase = rb * RT;
    const float4* Ws4 = (const float4*)Ws;

    float acc[RT][4];
#pragma unroll
    for (int r = 0; r < RT; r++) { acc[r][0] = acc[r][1] = acc[r][2] = acc[r][3] = 0.f; }

#pragma unroll 4
    for (int k4 = 0; k4 < 32; k4++) {
        float4 a4[RT];
#pragma unroll
        for (int r = 0; r < RT; r++) a4[r] = As4[(rbase + r) * 32 + k4];
#pragma unroll
        for (int j = 0; j < 4; j++) {
            float4 w = Ws4[(k4 * 4 + j) * CB + cb];
#pragma unroll
            for (int r = 0; r < RT; r++) {
                float av = (j == 0) ? a4[r].x : (j == 1) ? a4[r].y : (j == 2) ? a4[r].z : a4[r].w;
                acc[r][0] = fmaf(av, w.x, acc[r][0]);
                acc[r][1] = fmaf(av, w.y, acc[r][1]);
                acc[r][2] = fmaf(av, w.z, acc[r][2]);
                acc[r][3] = fmaf(av, w.w, acc[r][3]);
            }
        }
    }

    float4* C4 = (float4*)C;
#pragma unroll
    for (int r = 0; r < RT; r++) {
        int row = row0 + rbase + r;
        if (row < N)
            C4[(size_t)row * CB + cb] = make_float4(acc[r][0], acc[r][1], acc[r][2], acc[r][3]);
    }
}

// ---------------- CSR build ----------------
__global__ void zero_cnt_kernel(int* __restrict__ cnt, int n, unsigned* __restrict__ M) {
    int i = blockIdx.x * blockDim.x + threadIdx.x;
    if (i < n) cnt[i] = 0;
    if (i < 2) M[i] = 0u;
}

__global__ void hist_kernel(const int* __restrict__ dst, int* __restrict__ cnt, int E) {
    int e = blockIdx.x * blockDim.x + threadIdx.x;
    if (e < E) atomicAdd(&cnt[dst[e]], 1);
}

// single block, 1024 threads: exclusive scan of cnt[0..N) into ptr, copy to cur
__global__ void scan_kernel(const int* __restrict__ cnt, int* __restrict__ ptr,
                            int* __restrict__ cur, int N) {
    __shared__ int part[1024];
    const int tid = threadIdx.x;
    const int chunk = (N + 1023) / 1024;
    const int b = tid * chunk;
    int s = 0;
    for (int i = 0; i < chunk; i++)
        if (b + i < N) s += cnt[b + i];
    part[tid] = s;
    __syncthreads();
    // inclusive Hillis-Steele scan
    for (int off = 1; off < 1024; off <<= 1) {
        int v = (tid >= off) ? part[tid - off] : 0;
        __syncthreads();
        part[tid] += v;
        __syncthreads();
    }
    int run = (tid > 0) ? part[tid - 1] : 0;
    for (int i = 0; i < chunk; i++) {
        if (b + i < N) {
            ptr[b + i] = run;
            cur[b + i] = run;
            run += cnt[b + i];
        }
    }
    if (tid == 1023) ptr[N] = part[1023];
}

__global__ void scatter_kernel(const int* __restrict__ src, const int* __restrict__ dst,
                               int* __restrict__ cur, int* __restrict__ csr, int E) {
    int e = blockIdx.x * blockDim.x + threadIdx.x;
    if (e >= E) return;
    int p = atomicAdd(&cur[dst[e]], 1);
    csr[p] = src[e];
}

// ---------------- per-node attention score + global max ----------------
template <int H, int F>
__global__ void score_kernel(const float* __restrict__ feat,
                             const float* __restrict__ attn,
                             float* __restrict__ s,
                             unsigned* __restrict__ M, int N) {
    constexpr int NV4 = H * F / 4;
    constexpr int LPH = F / 4;
    int gid  = blockIdx.x * blockDim.x + threadIdx.x;
    int node = gid >> 5;
    int lane = gid & 31;
    if (node >= N) return;
    float p = 0.f;
    if (lane < NV4) {
        float4 f = ((const float4*)feat)[(size_t)node * NV4 + lane];
        float4 a = ((const float4*)attn)[lane];
        p = f.x * a.x + f.y * a.y + f.z * a.z + f.w * a.w;
    }
#pragma unroll
    for (int off = LPH / 2; off >= 1; off >>= 1)
        p += __shfl_xor_sync(0xffffffffu, p, off);
    if (lane < NV4 && (lane % LPH) == 0) {
        int h = lane / LPH;
        float sv = p > 0.f ? p : 0.2f * p;
        s[(size_t)node * H + h] = sv;
        atomicMax(&M[h], enc_f(sv));
    }
}

// ---------------- t = exp(s - M) ----------------
template <int H>
__global__ void exp_kernel(const float* __restrict__ s,
                           const unsigned* __restrict__ M,
                           float* __restrict__ t, int total) {
    int i = blockIdx.x * blockDim.x + threadIdx.x;
    if (i >= total) return;
    int h = (H == 2) ? (i & 1) : 0;
    t[i] = __expf(s[i] - dec_f(M[h]));
}

// ---------------- gather aggregation: warp per dst node ----------------
// out[node] = relu?( sum_e w_e * feat[src_e] + bias ),  w_e = t[src_e]/denom
template <int H, int F, bool RELU>
__global__ void node_kernel(const int* __restrict__ ptr,
                            const int* __restrict__ csr,
                            const float* __restrict__ feat,
                            const float* __restrict__ t,
                            const float* __restrict__ bias,
                            float* __restrict__ out, int N) {
    constexpr int NV4 = H * F / 4;            // 32 (H=2) or 16 (H=1)
    int gid  = blockIdx.x * blockDim.x + threadIdx.x;
    int node = gid >> 5;
    int lane = gid & 31;
    if (node >= N) return;
    const int beg = ptr[node];
    const int end = ptr[node + 1];

    // pass 1: denominators
    float d0 = 0.f, d1 = 0.f;
    for (int i = beg + lane; i < end; i += 32) {
        int u = __ldg(&csr[i]);
        if (H == 2) {
            float2 tv = ((const float2*)t)[u];
            d0 += tv.x; d1 += tv.y;
        } else {
            d0 += __ldg(&t[u]);
        }
    }
#pragma unroll
    for (int off = 16; off >= 1; off >>= 1) {
        d0 += __shfl_xor_sync(0xffffffffu, d0, off);
        if (H == 2) d1 += __shfl_xor_sync(0xffffffffu, d1, off);
    }
    const int h = (H == 2) ? (lane >> 4) : 0;
    float den = (H == 2 && h == 1) ? d1 : d0;
    float inv = den > 0.f ? __frcp_rn(den) : 0.f;

    // pass 2: weighted gather
    float4 acc = make_float4(0.f, 0.f, 0.f, 0.f);
#pragma unroll 2
    for (int i = beg; i < end; i++) {
        int u = __ldg(&csr[i]);
        float w = __ldg(&t[(size_t)u * H + h]) * inv;
        if (lane < NV4) {
            float4 f = ((const float4*)feat)[(size_t)u * NV4 + lane];
            acc.x = fmaf(f.x, w, acc.x);
            acc.y = fmaf(f.y, w, acc.y);
            acc.z = fmaf(f.z, w, acc.z);
            acc.w = fmaf(f.w, w, acc.w);
        }
    }

    if (lane < NV4) {
        float4 b = ((const float4*)bias)[lane];
        acc.x += b.x; acc.y += b.y; acc.z += b.z; acc.w += b.w;
        if (RELU) {
            acc.x = fmaxf(acc.x, 0.f); acc.y = fmaxf(acc.y, 0.f);
            acc.z = fmaxf(acc.z, 0.f); acc.w = fmaxf(acc.w, 0.f);
        }
        ((float4*)out)[(size_t)node * NV4 + lane] = acc;
    }
}

// ---------------------------------------------------------------------------
extern "C" void kernel_launch(void* const* d_in, const int* in_sizes, int n_in,
                              void* d_out, int out_size) {
    const float* feat    = (const float*)d_in[0];
    const float* W0      = (const float*)d_in[1];
    const float* attn_l0 = (const float*)d_in[2];
    const float* bias0   = (const float*)d_in[3];
    const float* W1      = (const float*)d_in[4];
    const float* attn_l1 = (const float*)d_in[5];
    const float* bias1   = (const float*)d_in[6];
    const float* W2      = (const float*)d_in[7];
    const float* attn_l2 = (const float*)d_in[8];
    const float* bias2   = (const float*)d_in[9];
    const int*   src     = (const int*)d_in[10];
    const int*   dst     = (const int*)d_in[11];

    const int N = in_sizes[0] / 128;
    const int E = in_sizes[10];

    float *p_feat, *p_hid, *p_s, *p_t;
    unsigned* p_M;
    int *p_cnt, *p_ptr, *p_cur, *p_csr;
    cudaGetSymbolAddress((void**)&p_feat, g_feat);
    cudaGetSymbolAddress((void**)&p_hid,  g_hid);
    cudaGetSymbolAddress((void**)&p_s,    g_s);
    cudaGetSymbolAddress((void**)&p_t,    g_t);
    cudaGetSymbolAddress((void**)&p_M,    g_M);
    cudaGetSymbolAddress((void**)&p_cnt,  g_cnt);
    cudaGetSymbolAddress((void**)&p_ptr,  g_ptr);
    cudaGetSymbolAddress((void**)&p_cur,  g_cur);
    cudaGetSymbolAddress((void**)&p_csr,  g_csr);

    const int SM128 = (64 * 128 + 128 * 128) * 4;  // 96 KB
    const int SM64  = (64 * 128 + 128 * 64) * 4;   // 64 KB
    cudaFuncSetAttribute(gemm_kernel<128>, cudaFuncAttributeMaxDynamicSharedMemorySize, SM128);
    cudaFuncSetAttribute(gemm_kernel<64>,  cudaFuncAttributeMaxDynamicSharedMemorySize, SM64);

    const int gGemm  = (N + 63) / 64;
    const int gScore = (N * 32 + 255) / 256;
    const int gEdge  = (E + 255) / 256;
    const int gNode  = (N * 32 + 255) / 256;

    // -------- CSR build (shared by all layers) + M init for layer 0 --------
    zero_cnt_kernel<<<(N + 1 + 255) / 256, 256>>>(p_cnt, N + 1, p_M);
    hist_kernel<<<gEdge, 256>>>(dst, p_cnt, E);
    scan_kernel<<<1, 1024>>>(p_cnt, p_ptr, p_cur, N);
    scatter_kernel<<<gEdge, 256>>>(src, dst, p_cur, p_csr, E);

    // -------- layer 0 --------
    gemm_kernel<128><<<gGemm, 256, SM128>>>(feat, W0, p_feat, N);
    score_kernel<2, 64><<<gScore, 256>>>(p_feat, attn_l0, p_s, p_M, N);
    exp_kernel<2><<<(N * 2 + 255) / 256, 256>>>(p_s, p_M, p_t, N * 2);
    node_kernel<2, 64, true><<<gNode, 256>>>(p_ptr, p_csr, p_feat, p_t, bias0, p_hid, N);

    // -------- layer 1 --------
    zero_cnt_kernel<<<1, 256>>>(p_cnt, 0, p_M);  // reset M only
    gemm_kernel<128><<<gGemm, 256, SM128>>>(p_hid, W1, p_feat, N);
    score_kernel<2, 64><<<gScore, 256>>>(p_feat, attn_l1, p_s, p_M, N);
    exp_kernel<2><<<(N * 2 + 255) / 256, 256>>>(p_s, p_M, p_t, N * 2);
    node_kernel<2, 64, true><<<gNode, 256>>>(p_ptr, p_csr, p_feat, p_t, bias1, p_hid, N);

    // -------- layer 2 (single head, no relu, write d_out) --------
    zero_cnt_kernel<<<1, 256>>>(p_cnt, 0, p_M);  // reset M only
    gemm_kernel<64><<<gGemm, 256, SM64>>>(p_hid, W2, p_feat, N);
    score_kernel<1, 64><<<gScore, 256>>>(p_feat, attn_l2, p_s, p_M, N);
    exp_kernel<1><<<(N + 255) / 256, 256>>>(p_s, p_M, p_t, N);
    node_kernel<1, 64, false><<<gNode, 256>>>(p_ptr, p_csr, p_feat, p_t, bias2, (float*)d_out, N);
}

// round 3
// speedup vs baseline: 1.6317x; 1.1804x over previous
#include <cuda_runtime.h>
#include <cstdint>

// ---------------------------------------------------------------------------
// GAT 3-layer forward, gather-based (CSR by dst), no float atomics.
// R3: high-throughput double-buffered SGEMM (128x128 tile, 8x8/thread).
// ---------------------------------------------------------------------------

#define MAXN 50000
#define MAXE 800000
#define MAXW 128

__device__ float g_feat[MAXN * MAXW];
__device__ float g_hid [MAXN * MAXW];
__device__ float g_s   [MAXN * 2];
__device__ float g_t   [MAXN * 2];
__device__ unsigned g_M[2];
__device__ int g_cnt[MAXN + 1];
__device__ int g_ptr[MAXN + 1];
__device__ int g_cur[MAXN + 1];
__device__ int g_csr[MAXE];

__device__ __forceinline__ unsigned enc_f(float f) {
    unsigned u = __float_as_uint(f);
    return (u & 0x80000000u) ? ~u : (u | 0x80000000u);
}
__device__ __forceinline__ float dec_f(unsigned u) {
    return (u & 0x80000000u) ? __uint_as_float(u ^ 0x80000000u)
                             : __uint_as_float(~u);
}

// ---------------- SGEMM: C[N][BN] = A[N][128] @ W[BN][128]^T ----------------
// Block tile BM=128 x BN, BK=16, per-thread 8x8 register tile, double-buffered
// smem with transposed (k-major) layout for conflict-free float4 reads.
template <int BN>
__global__ void gemm_kernel(const float* __restrict__ A,
                            const float* __restrict__ W,
                            float* __restrict__ C, int N) {
    constexpr int BM = 128, BK = 16, TM = 8, TN = 8, K = 128;
    constexpr int THREADS = (BM / TM) * (BN / TN);   // 256 (BN=128) / 128 (BN=64)
    constexpr int KT = K / BK;                        // 8
    constexpr int LA = BM * BK / 4 / THREADS;         // A float4 loads per thread
    constexpr int LW = BN * BK / 4 / THREADS;         // W float4 loads per thread

    __shared__ float As[2][BK * BM];
    __shared__ float Ws[2][BK * BN];

    const int tid  = threadIdx.x;
    const int tx   = tid % (BN / TN);
    const int ty   = tid / (BN / TN);
    const int row0 = blockIdx.x * BM;

    const float4* A4 = (const float4*)A;
    const float4* W4 = (const float4*)W;

    float4 rA[LA], rW[LW];

    // prologue: load tile 0
    {
#pragma unroll
        for (int i = 0; i < LA; i++) {
            int f = tid + i * THREADS;
            int r = f >> 2, c4 = f & 3;
            rA[i] = (row0 + r < N) ? A4[(size_t)(row0 + r) * 32 + c4]
                                   : make_float4(0.f, 0.f, 0.f, 0.f);
        }
#pragma unroll
        for (int i = 0; i < LW; i++) {
            int f = tid + i * THREADS;
            int n = f >> 2, c4 = f & 3;
            rW[i] = W4[(size_t)n * 32 + c4];
        }
#pragma unroll
        for (int i = 0; i < LA; i++) {
            int f = tid + i * THREADS;
            int r = f >> 2, c4 = f & 3;
            As[0][(c4 * 4 + 0) * BM + r] = rA[i].x;
            As[0][(c4 * 4 + 1) * BM + r] = rA[i].y;
            As[0][(c4 * 4 + 2) * BM + r] = rA[i].z;
            As[0][(c4 * 4 + 3) * BM + r] = rA[i].w;
        }
#pragma unroll
        for (int i = 0; i < LW; i++) {
            int f = tid + i * THREADS;
            int n = f >> 2, c4 = f & 3;
            Ws[0][(c4 * 4 + 0) * BN + n] = rW[i].x;
            Ws[0][(c4 * 4 + 1) * BN + n] = rW[i].y;
            Ws[0][(c4 * 4 + 2) * BN + n] = rW[i].z;
            Ws[0][(c4 * 4 + 3) * BN + n] = rW[i].w;
        }
    }
    __syncthreads();

    float acc[TM][TN];
#pragma unroll
    for (int i = 0; i < TM; i++)
#pragma unroll
        for (int j = 0; j < TN; j++) acc[i][j] = 0.f;

    for (int kt = 0; kt < KT; kt++) {
        const int cur = kt & 1;
        // prefetch next tile into registers
        if (kt + 1 < KT) {
#pragma unroll
            for (int i = 0; i < LA; i++) {
                int f = tid + i * THREADS;
                int r = f >> 2, c4 = f & 3;
                rA[i] = (row0 + r < N)
                        ? A4[(size_t)(row0 + r) * 32 + (kt + 1) * 4 + c4]
                        : make_float4(0.f, 0.f, 0.f, 0.f);
            }
#pragma unroll
            for (int i = 0; i < LW; i++) {
                int f = tid + i * THREADS;
                int n = f >> 2, c4 = f & 3;
                rW[i] = W4[(size_t)n * 32 + (kt + 1) * 4 + c4];
            }
        }
        // compute current tile
#pragma unroll
        for (int k = 0; k < BK; k++) {
            float4 a0 = *(const float4*)&As[cur][k * BM + ty * TM];
            float4 a1 = *(const float4*)&As[cur][k * BM + ty * TM + 4];
            float4 b0 = *(const float4*)&Ws[cur][k * BN + tx * TN];
            float4 b1 = *(const float4*)&Ws[cur][k * BN + tx * TN + 4];
            float av[TM] = {a0.x, a0.y, a0.z, a0.w, a1.x, a1.y, a1.z, a1.w};
            float bv[TN] = {b0.x, b0.y, b0.z, b0.w, b1.x, b1.y, b1.z, b1.w};
#pragma unroll
            for (int i = 0; i < TM; i++)
#pragma unroll
                for (int j = 0; j < TN; j++)
                    acc[i][j] = fmaf(av[i], bv[j], acc[i][j]);
        }
        // store next tile
        if (kt + 1 < KT) {
            const int nxt = cur ^ 1;
            __syncthreads();
#pragma unroll
            for (int i = 0; i < LA; i++) {
                int f = tid + i * THREADS;
                int r = f >> 2, c4 = f & 3;
                As[nxt][(c4 * 4 + 0) * BM + r] = rA[i].x;
                As[nxt][(c4 * 4 + 1) * BM + r] = rA[i].y;
                As[nxt][(c4 * 4 + 2) * BM + r] = rA[i].z;
                As[nxt][(c4 * 4 + 3) * BM + r] = rA[i].w;
            }
#pragma unroll
            for (int i = 0; i < LW; i++) {
                int f = tid + i * THREADS;
                int n = f >> 2, c4 = f & 3;
                Ws[nxt][(c4 * 4 + 0) * BN + n] = rW[i].x;
                Ws[nxt][(c4 * 4 + 1) * BN + n] = rW[i].y;
                Ws[nxt][(c4 * 4 + 2) * BN + n] = rW[i].z;
                Ws[nxt][(c4 * 4 + 3) * BN + n] = rW[i].w;
            }
            __syncthreads();
        }
    }

    float4* C4 = (float4*)C;
#pragma unroll
    for (int i = 0; i < TM; i++) {
        int row = row0 + ty * TM + i;
        if (row < N) {
            C4[(size_t)row * (BN / 4) + tx * 2 + 0] =
                make_float4(acc[i][0], acc[i][1], acc[i][2], acc[i][3]);
            C4[(size_t)row * (BN / 4) + tx * 2 + 1] =
                make_float4(acc[i][4], acc[i][5], acc[i][6], acc[i][7]);
        }
    }
}

// ---------------- CSR build ----------------
__global__ void zero_cnt_kernel(int* __restrict__ cnt, int n, unsigned* __restrict__ M) {
    int i = blockIdx.x * blockDim.x + threadIdx.x;
    if (i < n) cnt[i] = 0;
    if (i < 2) M[i] = 0u;
}

__global__ void hist_kernel(const int* __restrict__ dst, int* __restrict__ cnt, int E) {
    int e = blockIdx.x * blockDim.x + threadIdx.x;
    if (e < E) atomicAdd(&cnt[dst[e]], 1);
}

__global__ void scan_kernel(const int* __restrict__ cnt, int* __restrict__ ptr,
                            int* __restrict__ cur, int N) {
    __shared__ int part[1024];
    const int tid = threadIdx.x;
    const int chunk = (N + 1023) / 1024;
    const int b = tid * chunk;
    int s = 0;
    for (int i = 0; i < chunk; i++)
        if (b + i < N) s += cnt[b + i];
    part[tid] = s;
    __syncthreads();
    for (int off = 1; off < 1024; off <<= 1) {
        int v = (tid >= off) ? part[tid - off] : 0;
        __syncthreads();
        part[tid] += v;
        __syncthreads();
    }
    int run = (tid > 0) ? part[tid - 1] : 0;
    for (int i = 0; i < chunk; i++) {
        if (b + i < N) {
            ptr[b + i] = run;
            cur[b + i] = run;
            run += cnt[b + i];
        }
    }
    if (tid == 1023) ptr[N] = part[1023];
}

__global__ void scatter_kernel(const int* __restrict__ src, const int* __restrict__ dst,
                               int* __restrict__ cur, int* __restrict__ csr, int E) {
    int e = blockIdx.x * blockDim.x + threadIdx.x;
    if (e >= E) return;
    int p = atomicAdd(&cur[dst[e]], 1);
    csr[p] = src[e];
}

// ---------------- per-node attention score + global max ----------------
template <int H, int F>
__global__ void score_kernel(const float* __restrict__ feat,
                             const float* __restrict__ attn,
                             float* __restrict__ s,
                             unsigned* __restrict__ M, int N) {
    constexpr int NV4 = H * F / 4;
    constexpr int LPH = F / 4;
    int gid  = blockIdx.x * blockDim.x + threadIdx.x;
    int node = gid >> 5;
    int lane = gid & 31;
    if (node >= N) return;
    float p = 0.f;
    if (lane < NV4) {
        float4 f = ((const float4*)feat)[(size_t)node * NV4 + lane];
        float4 a = ((const float4*)attn)[lane];
        p = f.x * a.x + f.y * a.y + f.z * a.z + f.w * a.w;
    }
#pragma unroll
    for (int off = LPH / 2; off >= 1; off >>= 1)
        p += __shfl_xor_sync(0xffffffffu, p, off);
    if (lane < NV4 && (lane % LPH) == 0) {
        int h = lane / LPH;
        float sv = p > 0.f ? p : 0.2f * p;
        s[(size_t)node * H + h] = sv;
        atomicMax(&M[h], enc_f(sv));
    }
}

// ---------------- t = exp(s - M) ----------------
template <int H>
__global__ void exp_kernel(const float* __restrict__ s,
                           const unsigned* __restrict__ M,
                           float* __restrict__ t, int total) {
    int i = blockIdx.x * blockDim.x + threadIdx.x;
    if (i >= total) return;
    int h = (H == 2) ? (i & 1) : 0;
    t[i] = __expf(s[i] - dec_f(M[h]));
}

// ---------------- gather aggregation: warp per dst node ----------------
template <int H, int F, bool RELU>
__global__ void node_kernel(const int* __restrict__ ptr,
                            const int* __restrict__ csr,
                            const float* __restrict__ feat,
                            const float* __restrict__ t,
                            const float* __restrict__ bias,
                            float* __restrict__ out, int N) {
    constexpr int NV4 = H * F / 4;
    int gid  = blockIdx.x * blockDim.x + threadIdx.x;
    int node = gid >> 5;
    int lane = gid & 31;
    if (node >= N) return;
    const int beg = ptr[node];
    const int end = ptr[node + 1];

    float d0 = 0.f, d1 = 0.f;
    for (int i = beg + lane; i < end; i += 32) {
        int u = __ldg(&csr[i]);
        if (H == 2) {
            float2 tv = ((const float2*)t)[u];
            d0 += tv.x; d1 += tv.y;
        } else {
            d0 += __ldg(&t[u]);
        }
    }
#pragma unroll
    for (int off = 16; off >= 1; off >>= 1) {
        d0 += __shfl_xor_sync(0xffffffffu, d0, off);
        if (H == 2) d1 += __shfl_xor_sync(0xffffffffu, d1, off);
    }
    const int h = (H == 2) ? (lane >> 4) : 0;
    float den = (H == 2 && h == 1) ? d1 : d0;
    float inv = den > 0.f ? __frcp_rn(den) : 0.f;

    float4 acc = make_float4(0.f, 0.f, 0.f, 0.f);
#pragma unroll 2
    for (int i = beg; i < end; i++) {
        int u = __ldg(&csr[i]);
        float w = __ldg(&t[(size_t)u * H + h]) * inv;
        if (lane < NV4) {
            float4 f = ((const float4*)feat)[(size_t)u * NV4 + lane];
            acc.x = fmaf(f.x, w, acc.x);
            acc.y = fmaf(f.y, w, acc.y);
            acc.z = fmaf(f.z, w, acc.z);
            acc.w = fmaf(f.w, w, acc.w);
        }
    }

    if (lane < NV4) {
        float4 b = ((const float4*)bias)[lane];
        acc.x += b.x; acc.y += b.y; acc.z += b.z; acc.w += b.w;
        if (RELU) {
            acc.x = fmaxf(acc.x, 0.f); acc.y = fmaxf(acc.y, 0.f);
            acc.z = fmaxf(acc.z, 0.f); acc.w = fmaxf(acc.w, 0.f);
        }
        ((float4*)out)[(size_t)node * NV4 + lane] = acc;
    }
}

// ---------------------------------------------------------------------------
extern "C" void kernel_launch(void* const* d_in, const int* in_sizes, int n_in,
                              void* d_out, int out_size) {
    const float* feat    = (const float*)d_in[0];
    const float* W0      = (const float*)d_in[1];
    const float* attn_l0 = (const float*)d_in[2];
    const float* bias0   = (const float*)d_in[3];
    const float* W1      = (const float*)d_in[4];
    const float* attn_l1 = (const float*)d_in[5];
    const float* bias1   = (const float*)d_in[6];
    const float* W2      = (const float*)d_in[7];
    const float* attn_l2 = (const float*)d_in[8];
    const float* bias2   = (const float*)d_in[9];
    const int*   src     = (const int*)d_in[10];
    const int*   dst     = (const int*)d_in[11];

    const int N = in_sizes[0] / 128;
    const int E = in_sizes[10];

    float *p_feat, *p_hid, *p_s, *p_t;
    unsigned* p_M;
    int *p_cnt, *p_ptr, *p_cur, *p_csr;
    cudaGetSymbolAddress((void**)&p_feat, g_feat);
    cudaGetSymbolAddress((void**)&p_hid,  g_hid);
    cudaGetSymbolAddress((void**)&p_s,    g_s);
    cudaGetSymbolAddress((void**)&p_t,    g_t);
    cudaGetSymbolAddress((void**)&p_M,    g_M);
    cudaGetSymbolAddress((void**)&p_cnt,  g_cnt);
    cudaGetSymbolAddress((void**)&p_ptr,  g_ptr);
    cudaGetSymbolAddress((void**)&p_cur,  g_cur);
    cudaGetSymbolAddress((void**)&p_csr,  g_csr);

    const int gGemm  = (N + 127) / 128;
    const int gScore = (N * 32 + 255) / 256;
    const int gEdge  = (E + 255) / 256;
    const int gNode  = (N * 32 + 255) / 256;

    // -------- CSR build (shared by all layers) + M init for layer 0 --------
    zero_cnt_kernel<<<(N + 1 + 255) / 256, 256>>>(p_cnt, N + 1, p_M);
    hist_kernel<<<gEdge, 256>>>(dst, p_cnt, E);
    scan_kernel<<<1, 1024>>>(p_cnt, p_ptr, p_cur, N);
    scatter_kernel<<<gEdge, 256>>>(src, dst, p_cur, p_csr, E);

    // -------- layer 0 --------
    gemm_kernel<128><<<gGemm, 256>>>(feat, W0, p_feat, N);
    score_kernel<2, 64><<<gScore, 256>>>(p_feat, attn_l0, p_s, p_M, N);
    exp_kernel<2><<<(N * 2 + 255) / 256, 256>>>(p_s, p_M, p_t, N * 2);
    node_kernel<2, 64, true><<<gNode, 256>>>(p_ptr, p_csr, p_feat, p_t, bias0, p_hid, N);

    // -------- layer 1 --------
    zero_cnt_kernel<<<1, 256>>>(p_cnt, 0, p_M);  // reset M only
    gemm_kernel<128><<<gGemm, 256>>>(p_hid, W1, p_feat, N);
    score_kernel<2, 64><<<gScore, 256>>>(p_feat, attn_l1, p_s, p_M, N);
    exp_kernel<2><<<(N * 2 + 255) / 256, 256>>>(p_s, p_M, p_t, N * 2);
    node_kernel<2, 64, true><<<gNode, 256>>>(p_ptr, p_csr, p_feat, p_t, bias1, p_hid, N);

    // -------- layer 2 (single head, no relu, write d_out) --------
    zero_cnt_kernel<<<1, 256>>>(p_cnt, 0, p_M);  // reset M only
    gemm_kernel<64><<<gGemm, 128>>>(p_hid, W2, p_feat, N);
    score_kernel<1, 64><<<gScore, 256>>>(p_feat, attn_l2, p_s, p_M, N);
    exp_kernel<1><<<(N + 255) / 256, 256>>>(p_s, p_M, p_t, N);
    node_kernel<1, 64, false><<<gNode, 256>>>(p_ptr, p_csr, p_feat, p_t, bias2, (float*)d_out, N);
}

// round 4
// speedup vs baseline: 1.6994x; 1.0415x over previous
#include <cuda_runtime.h>
#include <cstdint>

// ---------------------------------------------------------------------------
// GAT 3-layer forward, gather-based (CSR by dst), no float atomics.
// R4: single-pass normalize-at-end node gather, unroll-4, H=1 half-warps.
// ---------------------------------------------------------------------------

#define MAXN 50000
#define MAXE 800000
#define MAXW 128

__device__ float g_feat[MAXN * MAXW];
__device__ float g_hid [MAXN * MAXW];
__device__ float g_s   [MAXN * 2];
__device__ float g_t   [MAXN * 2];
__device__ unsigned g_M[2];
__device__ int g_cnt[MAXN + 1];
__device__ int g_ptr[MAXN + 1];
__device__ int g_cur[MAXN + 1];
__device__ int g_csr[MAXE];

__device__ __forceinline__ unsigned enc_f(float f) {
    unsigned u = __float_as_uint(f);
    return (u & 0x80000000u) ? ~u : (u | 0x80000000u);
}
__device__ __forceinline__ float dec_f(unsigned u) {
    return (u & 0x80000000u) ? __uint_as_float(u ^ 0x80000000u)
                             : __uint_as_float(~u);
}

// ---------------- SGEMM: C[N][BN] = A[N][128] @ W[BN][128]^T ----------------
template <int BN>
__global__ void gemm_kernel(const float* __restrict__ A,
                            const float* __restrict__ W,
                            float* __restrict__ C, int N) {
    constexpr int BM = 128, BK = 16, TM = 8, TN = 8, K = 128;
    constexpr int THREADS = (BM / TM) * (BN / TN);
    constexpr int KT = K / BK;
    constexpr int LA = BM * BK / 4 / THREADS;
    constexpr int LW = BN * BK / 4 / THREADS;

    __shared__ float As[2][BK * BM];
    __shared__ float Ws[2][BK * BN];

    const int tid  = threadIdx.x;
    const int tx   = tid % (BN / TN);
    const int ty   = tid / (BN / TN);
    const int row0 = blockIdx.x * BM;

    const float4* A4 = (const float4*)A;
    const float4* W4 = (const float4*)W;

    float4 rA[LA], rW[LW];

    {
#pragma unroll
        for (int i = 0; i < LA; i++) {
            int f = tid + i * THREADS;
            int r = f >> 2, c4 = f & 3;
            rA[i] = (row0 + r < N) ? A4[(size_t)(row0 + r) * 32 + c4]
                                   : make_float4(0.f, 0.f, 0.f, 0.f);
        }
#pragma unroll
        for (int i = 0; i < LW; i++) {
            int f = tid + i * THREADS;
            int n = f >> 2, c4 = f & 3;
            rW[i] = W4[(size_t)n * 32 + c4];
        }
#pragma unroll
        for (int i = 0; i < LA; i++) {
            int f = tid + i * THREADS;
            int r = f >> 2, c4 = f & 3;
            As[0][(c4 * 4 + 0) * BM + r] = rA[i].x;
            As[0][(c4 * 4 + 1) * BM + r] = rA[i].y;
            As[0][(c4 * 4 + 2) * BM + r] = rA[i].z;
            As[0][(c4 * 4 + 3) * BM + r] = rA[i].w;
        }
#pragma unroll
        for (int i = 0; i < LW; i++) {
            int f = tid + i * THREADS;
            int n = f >> 2, c4 = f & 3;
            Ws[0][(c4 * 4 + 0) * BN + n] = rW[i].x;
            Ws[0][(c4 * 4 + 1) * BN + n] = rW[i].y;
            Ws[0][(c4 * 4 + 2) * BN + n] = rW[i].z;
            Ws[0][(c4 * 4 + 3) * BN + n] = rW[i].w;
        }
    }
    __syncthreads();

    float acc[TM][TN];
#pragma unroll
    for (int i = 0; i < TM; i++)
#pragma unroll
        for (int j = 0; j < TN; j++) acc[i][j] = 0.f;

    for (int kt = 0; kt < KT; kt++) {
        const int cur = kt & 1;
        if (kt + 1 < KT) {
#pragma unroll
            for (int i = 0; i < LA; i++) {
                int f = tid + i * THREADS;
                int r = f >> 2, c4 = f & 3;
                rA[i] = (row0 + r < N)
                        ? A4[(size_t)(row0 + r) * 32 + (kt + 1) * 4 + c4]
                        : make_float4(0.f, 0.f, 0.f, 0.f);
            }
#pragma unroll
            for (int i = 0; i < LW; i++) {
                int f = tid + i * THREADS;
                int n = f >> 2, c4 = f & 3;
                rW[i] = W4[(size_t)n * 32 + (kt + 1) * 4 + c4];
            }
        }
#pragma unroll
        for (int k = 0; k < BK; k++) {
            float4 a0 = *(const float4*)&As[cur][k * BM + ty * TM];
            float4 a1 = *(const float4*)&As[cur][k * BM + ty * TM + 4];
            float4 b0 = *(const float4*)&Ws[cur][k * BN + tx * TN];
            float4 b1 = *(const float4*)&Ws[cur][k * BN + tx * TN + 4];
            float av[TM] = {a0.x, a0.y, a0.z, a0.w, a1.x, a1.y, a1.z, a1.w};
            float bv[TN] = {b0.x, b0.y, b0.z, b0.w, b1.x, b1.y, b1.z, b1.w};
#pragma unroll
            for (int i = 0; i < TM; i++)
#pragma unroll
                for (int j = 0; j < TN; j++)
                    acc[i][j] = fmaf(av[i], bv[j], acc[i][j]);
        }
        if (kt + 1 < KT) {
            const int nxt = cur ^ 1;
            __syncthreads();
#pragma unroll
            for (int i = 0; i < LA; i++) {
                int f = tid + i * THREADS;
                int r = f >> 2, c4 = f & 3;
                As[nxt][(c4 * 4 + 0) * BM + r] = rA[i].x;
                As[nxt][(c4 * 4 + 1) * BM + r] = rA[i].y;
                As[nxt][(c4 * 4 + 2) * BM + r] = rA[i].z;
                As[nxt][(c4 * 4 + 3) * BM + r] = rA[i].w;
            }
#pragma unroll
            for (int i = 0; i < LW; i++) {
                int f = tid + i * THREADS;
                int n = f >> 2, c4 = f & 3;
                Ws[nxt][(c4 * 4 + 0) * BN + n] = rW[i].x;
                Ws[nxt][(c4 * 4 + 1) * BN + n] = rW[i].y;
                Ws[nxt][(c4 * 4 + 2) * BN + n] = rW[i].z;
                Ws[nxt][(c4 * 4 + 3) * BN + n] = rW[i].w;
            }
            __syncthreads();
        }
    }

    float4* C4 = (float4*)C;
#pragma unroll
    for (int i = 0; i < TM; i++) {
        int row = row0 + ty * TM + i;
        if (row < N) {
            C4[(size_t)row * (BN / 4) + tx * 2 + 0] =
                make_float4(acc[i][0], acc[i][1], acc[i][2], acc[i][3]);
            C4[(size_t)row * (BN / 4) + tx * 2 + 1] =
                make_float4(acc[i][4], acc[i][5], acc[i][6], acc[i][7]);
        }
    }
}

// ---------------- CSR build ----------------
__global__ void zero_cnt_kernel(int* __restrict__ cnt, int n, unsigned* __restrict__ M) {
    int i = blockIdx.x * blockDim.x + threadIdx.x;
    if (i < n) cnt[i] = 0;
    if (i < 2) M[i] = 0u;
}

__global__ void hist_kernel(const int* __restrict__ dst, int* __restrict__ cnt, int E) {
    int e = blockIdx.x * blockDim.x + threadIdx.x;
    if (e < E) atomicAdd(&cnt[dst[e]], 1);
}

__global__ void scan_kernel(const int* __restrict__ cnt, int* __restrict__ ptr,
                            int* __restrict__ cur, int N) {
    __shared__ int part[1024];
    const int tid = threadIdx.x;
    const int chunk = (N + 1023) / 1024;
    const int b = tid * chunk;
    int s = 0;
    for (int i = 0; i < chunk; i++)
        if (b + i < N) s += cnt[b + i];
    part[tid] = s;
    __syncthreads();
    for (int off = 1; off < 1024; off <<= 1) {
        int v = (tid >= off) ? part[tid - off] : 0;
        __syncthreads();
        part[tid] += v;
        __syncthreads();
    }
    int run = (tid > 0) ? part[tid - 1] : 0;
    for (int i = 0; i < chunk; i++) {
        if (b + i < N) {
            ptr[b + i] = run;
            cur[b + i] = run;
            run += cnt[b + i];
        }
    }
    if (tid == 1023) ptr[N] = part[1023];
}

__global__ void scatter_kernel(const int* __restrict__ src, const int* __restrict__ dst,
                               int* __restrict__ cur, int* __restrict__ csr, int E) {
    int e = blockIdx.x * blockDim.x + threadIdx.x;
    if (e >= E) return;
    int p = atomicAdd(&cur[dst[e]], 1);
    csr[p] = src[e];
}

// ---------------- per-node attention score + global max ----------------
template <int H, int F>
__global__ void score_kernel(const float* __restrict__ feat,
                             const float* __restrict__ attn,
                             float* __restrict__ s,
                             unsigned* __restrict__ M, int N) {
    constexpr int NV4 = H * F / 4;
    constexpr int LPH = F / 4;
    int gid  = blockIdx.x * blockDim.x + threadIdx.x;
    int node = gid >> 5;
    int lane = gid & 31;
    if (node >= N) return;
    float p = 0.f;
    if (lane < NV4) {
        float4 f = ((const float4*)feat)[(size_t)node * NV4 + lane];
        float4 a = ((const float4*)attn)[lane];
        p = f.x * a.x + f.y * a.y + f.z * a.z + f.w * a.w;
    }
#pragma unroll
    for (int off = LPH / 2; off >= 1; off >>= 1)
        p += __shfl_xor_sync(0xffffffffu, p, off);
    if (lane < NV4 && (lane % LPH) == 0) {
        int h = lane / LPH;
        float sv = p > 0.f ? p : 0.2f * p;
        s[(size_t)node * H + h] = sv;
        atomicMax(&M[h], enc_f(sv));
    }
}

// ---------------- t = exp(s - M) ----------------
template <int H>
__global__ void exp_kernel(const float* __restrict__ s,
                           const unsigned* __restrict__ M,
                           float* __restrict__ t, int total) {
    int i = blockIdx.x * blockDim.x + threadIdx.x;
    if (i >= total) return;
    int h = (H == 2) ? (i & 1) : 0;
    t[i] = __expf(s[i] - dec_f(M[h]));
}

// ---------------- gather aggregation: LPN lanes per dst node ----------------
// out[node] = relu?( (Σ_e t[src_e]·feat[src_e]) / (Σ_e t[src_e]) + bias )
template <int H, int F, bool RELU>
__global__ void node_kernel(const int* __restrict__ ptr,
                            const int* __restrict__ csr,
                            const float* __restrict__ feat,
                            const float* __restrict__ t,
                            const float* __restrict__ bias,
                            float* __restrict__ out, int N) {
    constexpr int LPN = H * F / 4;            // 32 (H=2) or 16 (H=1)
    int gid  = blockIdx.x * blockDim.x + threadIdx.x;
    int node = gid / LPN;
    int lane = gid % LPN;
    if (node >= N) return;
    const int beg = ptr[node];
    const int end = ptr[node + 1];
    const int h   = (H == 2) ? (lane >> 4) : 0;

    const float4* feat4 = (const float4*)feat;

    float4 acc = make_float4(0.f, 0.f, 0.f, 0.f);
    float  d   = 0.f;

    int i = beg;
    for (; i + 4 <= end; i += 4) {
        int u0 = __ldg(&csr[i + 0]);
        int u1 = __ldg(&csr[i + 1]);
        int u2 = __ldg(&csr[i + 2]);
        int u3 = __ldg(&csr[i + 3]);
        float t0 = __ldg(&t[(size_t)u0 * H + h]);
        float t1 = __ldg(&t[(size_t)u1 * H + h]);
        float t2 = __ldg(&t[(size_t)u2 * H + h]);
        float t3 = __ldg(&t[(size_t)u3 * H + h]);
        float4 f0 = feat4[(size_t)u0 * LPN + lane];
        float4 f1 = feat4[(size_t)u1 * LPN + lane];
        float4 f2 = feat4[(size_t)u2 * LPN + lane];
        float4 f3 = feat4[(size_t)u3 * LPN + lane];
        d += (t0 + t1) + (t2 + t3);
        acc.x = fmaf(t0, f0.x, acc.x); acc.y = fmaf(t0, f0.y, acc.y);
        acc.z = fmaf(t0, f0.z, acc.z); acc.w = fmaf(t0, f0.w, acc.w);
        acc.x = fmaf(t1, f1.x, acc.x); acc.y = fmaf(t1, f1.y, acc.y);
        acc.z = fmaf(t1, f1.z, acc.z); acc.w = fmaf(t1, f1.w, acc.w);
        acc.x = fmaf(t2, f2.x, acc.x); acc.y = fmaf(t2, f2.y, acc.y);
        acc.z = fmaf(t2, f2.z, acc.z); acc.w = fmaf(t2, f2.w, acc.w);
        acc.x = fmaf(t3, f3.x, acc.x); acc.y = fmaf(t3, f3.y, acc.y);
        acc.z = fmaf(t3, f3.z, acc.z); acc.w = fmaf(t3, f3.w, acc.w);
    }
    for (; i < end; i++) {
        int u = __ldg(&csr[i]);
        float tv = __ldg(&t[(size_t)u * H + h]);
        float4 f = feat4[(size_t)u * LPN + lane];
        d += tv;
        acc.x = fmaf(tv, f.x, acc.x); acc.y = fmaf(tv, f.y, acc.y);
        acc.z = fmaf(tv, f.z, acc.z); acc.w = fmaf(tv, f.w, acc.w);
    }

    float inv = d > 0.f ? __frcp_rn(d) : 0.f;
    float4 b = ((const float4*)bias)[lane];
    acc.x = fmaf(acc.x, inv, b.x);
    acc.y = fmaf(acc.y, inv, b.y);
    acc.z = fmaf(acc.z, inv, b.z);
    acc.w = fmaf(acc.w, inv, b.w);
    if (RELU) {
        acc.x = fmaxf(acc.x, 0.f); acc.y = fmaxf(acc.y, 0.f);
        acc.z = fmaxf(acc.z, 0.f); acc.w = fmaxf(acc.w, 0.f);
    }
    ((float4*)out)[(size_t)node * LPN + lane] = acc;
}

// ---------------------------------------------------------------------------
extern "C" void kernel_launch(void* const* d_in, const int* in_sizes, int n_in,
                              void* d_out, int out_size) {
    const float* feat    = (const float*)d_in[0];
    const float* W0      = (const float*)d_in[1];
    const float* attn_l0 = (const float*)d_in[2];
    const float* bias0   = (const float*)d_in[3];
    const float* W1      = (const float*)d_in[4];
    const float* attn_l1 = (const float*)d_in[5];
    const float* bias1   = (const float*)d_in[6];
    const float* W2      = (const float*)d_in[7];
    const float* attn_l2 = (const float*)d_in[8];
    const float* bias2   = (const float*)d_in[9];
    const int*   src     = (const int*)d_in[10];
    const int*   dst     = (const int*)d_in[11];

    const int N = in_sizes[0] / 128;
    const int E = in_sizes[10];

    float *p_feat, *p_hid, *p_s, *p_t;
    unsigned* p_M;
    int *p_cnt, *p_ptr, *p_cur, *p_csr;
    cudaGetSymbolAddress((void**)&p_feat, g_feat);
    cudaGetSymbolAddress((void**)&p_hid,  g_hid);
    cudaGetSymbolAddress((void**)&p_s,    g_s);
    cudaGetSymbolAddress((void**)&p_t,    g_t);
    cudaGetSymbolAddress((void**)&p_M,    g_M);
    cudaGetSymbolAddress((void**)&p_cnt,  g_cnt);
    cudaGetSymbolAddress((void**)&p_ptr,  g_ptr);
    cudaGetSymbolAddress((void**)&p_cur,  g_cur);
    cudaGetSymbolAddress((void**)&p_csr,  g_csr);

    const int gGemm   = (N + 127) / 128;
    const int gScore  = (N * 32 + 255) / 256;
    const int gEdge   = (E + 255) / 256;
    const int gNode32 = (N * 32 + 255) / 256;
    const int gNode16 = (N * 16 + 255) / 256;

    // -------- CSR build (shared by all layers) + M init for layer 0 --------
    zero_cnt_kernel<<<(N + 1 + 255) / 256, 256>>>(p_cnt, N + 1, p_M);
    hist_kernel<<<gEdge, 256>>>(dst, p_cnt, E);
    scan_kernel<<<1, 1024>>>(p_cnt, p_ptr, p_cur, N);
    scatter_kernel<<<gEdge, 256>>>(src, dst, p_cur, p_csr, E);

    // -------- layer 0 --------
    gemm_kernel<128><<<gGemm, 256>>>(feat, W0, p_feat, N);
    score_kernel<2, 64><<<gScore, 256>>>(p_feat, attn_l0, p_s, p_M, N);
    exp_kernel<2><<<(N * 2 + 255) / 256, 256>>>(p_s, p_M, p_t, N * 2);
    node_kernel<2, 64, true><<<gNode32, 256>>>(p_ptr, p_csr, p_feat, p_t, bias0, p_hid, N);

    // -------- layer 1 --------
    zero_cnt_kernel<<<1, 256>>>(p_cnt, 0, p_M);  // reset M only
    gemm_kernel<128><<<gGemm, 256>>>(p_hid, W1, p_feat, N);
    score_kernel<2, 64><<<gScore, 256>>>(p_feat, attn_l1, p_s, p_M, N);
    exp_kernel<2><<<(N * 2 + 255) / 256, 256>>>(p_s, p_M, p_t, N * 2);
    node_kernel<2, 64, true><<<gNode32, 256>>>(p_ptr, p_csr, p_feat, p_t, bias1, p_hid, N);

    // -------- layer 2 (single head, no relu, write d_out) --------
    zero_cnt_kernel<<<1, 256>>>(p_cnt, 0, p_M);  // reset M only
    gemm_kernel<64><<<gGemm, 128>>>(p_hid, W2, p_feat, N);
    score_kernel<1, 64><<<gScore, 256>>>(p_feat, attn_l2, p_s, p_M, N);
    exp_kernel<1><<<(N + 255) / 256, 256>>>(p_s, p_M, p_t, N);
    node_kernel<1, 64, false><<<gNode16, 256>>>(p_ptr, p_csr, p_feat, p_t, bias2, (float*)d_out, N);
}

// round 5
// speedup vs baseline: 2.3445x; 1.3796x over previous
#include <cuda_runtime.h>
#include <cuda_fp16.h>
#include <cstdint>

// ---------------------------------------------------------------------------
// GAT 3-layer forward, gather-based (CSR by dst).
// R5: GEMM epilogue fuses attention score t=exp(leakyrelu(feat.attn)) (no max
// subtraction -- scores are O(1), and the max cancels in the softmax ratio),
// and stores feat as fp16 to halve edge-gather traffic. fp32 accumulation.
// ---------------------------------------------------------------------------

#define MAXN 50000
#define MAXE 800000
#define MAXW 128

__device__ __half g_feat_h[MAXN * MAXW];
__device__ float  g_hid [MAXN * MAXW];
__device__ float  g_t   [MAXN * 2];
__device__ int g_cnt[MAXN + 1];
__device__ int g_ptr[MAXN + 1];
__device__ int g_cur[MAXN + 1];
__device__ int g_csr[MAXE];

// ---------------- SGEMM + fused score epilogue ----------------
// C_h[N][BN] (fp16) = A[N][128] @ W[BN][128]^T ;  t[N][H] = exp(lrelu(C.attn))
template <int BN, int H>
__global__ void gemm_kernel(const float* __restrict__ A,
                            const float* __restrict__ W,
                            const float* __restrict__ attn,
                            __half* __restrict__ C_h,
                            float* __restrict__ t, int N) {
    constexpr int BM = 128, BK = 16, TM = 8, TN = 8, K = 128;
    constexpr int THREADS = (BM / TM) * (BN / TN);
    constexpr int KT = K / BK;
    constexpr int LA = BM * BK / 4 / THREADS;
    constexpr int LW = BN * BK / 4 / THREADS;
    constexpr int F = BN / H;   // features per head (64)

    __shared__ float As[2][BK * BM];
    __shared__ float Ws[2][BK * BN];
    __shared__ float sm_el[BM * H];

    const int tid  = threadIdx.x;
    const int tx   = tid % (BN / TN);
    const int ty   = tid / (BN / TN);
    const int row0 = blockIdx.x * BM;

    for (int i = tid; i < BM * H; i += THREADS) sm_el[i] = 0.f;

    const float4* A4 = (const float4*)A;
    const float4* W4 = (const float4*)W;

    float4 rA[LA], rW[LW];

    {
#pragma unroll
        for (int i = 0; i < LA; i++) {
            int f = tid + i * THREADS;
            int r = f >> 2, c4 = f & 3;
            rA[i] = (row0 + r < N) ? A4[(size_t)(row0 + r) * 32 + c4]
                                   : make_float4(0.f, 0.f, 0.f, 0.f);
        }
#pragma unroll
        for (int i = 0; i < LW; i++) {
            int f = tid + i * THREADS;
            int n = f >> 2, c4 = f & 3;
            rW[i] = W4[(size_t)n * 32 + c4];
        }
#pragma unroll
        for (int i = 0; i < LA; i++) {
            int f = tid + i * THREADS;
            int r = f >> 2, c4 = f & 3;
            As[0][(c4 * 4 + 0) * BM + r] = rA[i].x;
            As[0][(c4 * 4 + 1) * BM + r] = rA[i].y;
            As[0][(c4 * 4 + 2) * BM + r] = rA[i].z;
            As[0][(c4 * 4 + 3) * BM + r] = rA[i].w;
        }
#pragma unroll
        for (int i = 0; i < LW; i++) {
            int f = tid + i * THREADS;
            int n = f >> 2, c4 = f & 3;
            Ws[0][(c4 * 4 + 0) * BN + n] = rW[i].x;
            Ws[0][(c4 * 4 + 1) * BN + n] = rW[i].y;
            Ws[0][(c4 * 4 + 2) * BN + n] = rW[i].z;
            Ws[0][(c4 * 4 + 3) * BN + n] = rW[i].w;
        }
    }
    __syncthreads();

    float acc[TM][TN];
#pragma unroll
    for (int i = 0; i < TM; i++)
#pragma unroll
        for (int j = 0; j < TN; j++) acc[i][j] = 0.f;

    for (int kt = 0; kt < KT; kt++) {
        const int cur = kt & 1;
        if (kt + 1 < KT) {
#pragma unroll
            for (int i = 0; i < LA; i++) {
                int f = tid + i * THREADS;
                int r = f >> 2, c4 = f & 3;
                rA[i] = (row0 + r < N)
                        ? A4[(size_t)(row0 + r) * 32 + (kt + 1) * 4 + c4]
                        : make_float4(0.f, 0.f, 0.f, 0.f);
            }
#pragma unroll
            for (int i = 0; i < LW; i++) {
                int f = tid + i * THREADS;
                int n = f >> 2, c4 = f & 3;
                rW[i] = W4[(size_t)n * 32 + (kt + 1) * 4 + c4];
            }
        }
#pragma unroll
        for (int k = 0; k < BK; k++) {
            float4 a0 = *(const float4*)&As[cur][k * BM + ty * TM];
            float4 a1 = *(const float4*)&As[cur][k * BM + ty * TM + 4];
            float4 b0 = *(const float4*)&Ws[cur][k * BN + tx * TN];
            float4 b1 = *(const float4*)&Ws[cur][k * BN + tx * TN + 4];
            float av[TM] = {a0.x, a0.y, a0.z, a0.w, a1.x, a1.y, a1.z, a1.w};
            float bv[TN] = {b0.x, b0.y, b0.z, b0.w, b1.x, b1.y, b1.z, b1.w};
#pragma unroll
            for (int i = 0; i < TM; i++)
#pragma unroll
                for (int j = 0; j < TN; j++)
                    acc[i][j] = fmaf(av[i], bv[j], acc[i][j]);
        }
        if (kt + 1 < KT) {
            const int nxt = cur ^ 1;
            __syncthreads();
#pragma unroll
            for (int i = 0; i < LA; i++) {
                int f = tid + i * THREADS;
                int r = f >> 2, c4 = f & 3;
                As[nxt][(c4 * 4 + 0) * BM + r] = rA[i].x;
                As[nxt][(c4 * 4 + 1) * BM + r] = rA[i].y;
                As[nxt][(c4 * 4 + 2) * BM + r] = rA[i].z;
                As[nxt][(c4 * 4 + 3) * BM + r] = rA[i].w;
            }
#pragma unroll
            for (int i = 0; i < LW; i++) {
                int f = tid + i * THREADS;
                int n = f >> 2, c4 = f & 3;
                Ws[nxt][(c4 * 4 + 0) * BN + n] = rW[i].x;
                Ws[nxt][(c4 * 4 + 1) * BN + n] = rW[i].y;
                Ws[nxt][(c4 * 4 + 2) * BN + n] = rW[i].z;
                Ws[nxt][(c4 * 4 + 3) * BN + n] = rW[i].w;
            }
            __syncthreads();
        }
    }

    // store fp16 feat + score partials
    const int col0 = tx * TN;
    float av[TN];
#pragma unroll
    for (int j = 0; j < TN; j++) av[j] = attn[col0 + j];
    const int h = col0 / F;

#pragma unroll
    for (int i = 0; i < TM; i++) {
        int r   = ty * TM + i;
        int row = row0 + r;
        float part = 0.f;
#pragma unroll
        for (int j = 0; j < TN; j++) part += acc[i][j] * av[j];
        atomicAdd(&sm_el[r * H + h], part);
        if (row < N) {
            __half hv[TN];
#pragma unroll
            for (int j = 0; j < TN; j++) hv[j] = __float2half(acc[i][j]);
            *(uint4*)&C_h[(size_t)row * BN + col0] = *(uint4*)hv;
        }
    }
    __syncthreads();
    for (int i = tid; i < BM * H; i += THREADS) {
        int r = i / H, hh = i % H;
        int row = row0 + r;
        if (row < N) {
            float el = sm_el[i];
            float sv = el > 0.f ? el : 0.2f * el;
            t[(size_t)row * H + hh] = __expf(sv);
        }
    }
}

// ---------------- CSR build ----------------
__global__ void zero_cnt_kernel(int* __restrict__ cnt, int n) {
    int i = blockIdx.x * blockDim.x + threadIdx.x;
    if (i < n) cnt[i] = 0;
}

__global__ void hist_kernel(const int* __restrict__ dst, int* __restrict__ cnt, int E) {
    int e = blockIdx.x * blockDim.x + threadIdx.x;
    if (e < E) atomicAdd(&cnt[dst[e]], 1);
}

__global__ void scan_kernel(const int* __restrict__ cnt, int* __restrict__ ptr,
                            int* __restrict__ cur, int N) {
    __shared__ int part[1024];
    const int tid = threadIdx.x;
    const int chunk = (N + 1023) / 1024;
    const int b = tid * chunk;
    int s = 0;
    for (int i = 0; i < chunk; i++)
        if (b + i < N) s += cnt[b + i];
    part[tid] = s;
    __syncthreads();
    for (int off = 1; off < 1024; off <<= 1) {
        int v = (tid >= off) ? part[tid - off] : 0;
        __syncthreads();
        part[tid] += v;
        __syncthreads();
    }
    int run = (tid > 0) ? part[tid - 1] : 0;
    for (int i = 0; i < chunk; i++) {
        if (b + i < N) {
            ptr[b + i] = run;
            cur[b + i] = run;
            run += cnt[b + i];
        }
    }
    if (tid == 1023) ptr[N] = part[1023];
}

__global__ void scatter_kernel(const int* __restrict__ src, const int* __restrict__ dst,
                               int* __restrict__ cur, int* __restrict__ csr, int E) {
    int e = blockIdx.x * blockDim.x + threadIdx.x;
    if (e >= E) return;
    int p = atomicAdd(&cur[dst[e]], 1);
    csr[p] = src[e];
}

// ---------------- gather aggregation: LPN lanes per dst node ----------------
// out[node] = relu?( (Σ_e t[src_e]·feat[src_e]) / (Σ_e t[src_e]) + bias )
// feat is fp16 (8 halves / lane), accumulation fp32.
template <int H, int F, bool RELU>
__global__ void node_kernel(const int* __restrict__ ptr,
                            const int* __restrict__ csr,
                            const __half* __restrict__ feath,
                            const float* __restrict__ t,
                            const float* __restrict__ bias,
                            float* __restrict__ out, int N) {
    constexpr int LPN = H * F / 8;            // 16 (H=2) or 8 (H=1)
    int gid  = blockIdx.x * blockDim.x + threadIdx.x;
    int node = gid / LPN;
    int lane = gid % LPN;
    if (node >= N) return;
    const int beg = ptr[node];
    const int end = ptr[node + 1];
    const int h   = (H == 2) ? (lane >> 3) : 0;

    const uint4* feat8 = (const uint4*)feath;   // 8 halves per uint4

    float acc[8];
#pragma unroll
    for (int k = 0; k < 8; k++) acc[k] = 0.f;
    float d = 0.f;

    int i = beg;
    for (; i + 4 <= end; i += 4) {
        int u0 = __ldg(&csr[i + 0]);
        int u1 = __ldg(&csr[i + 1]);
        int u2 = __ldg(&csr[i + 2]);
        int u3 = __ldg(&csr[i + 3]);
        float t0 = __ldg(&t[(size_t)u0 * H + h]);
        float t1 = __ldg(&t[(size_t)u1 * H + h]);
        float t2 = __ldg(&t[(size_t)u2 * H + h]);
        float t3 = __ldg(&t[(size_t)u3 * H + h]);
        uint4 v0 = feat8[(size_t)u0 * LPN + lane];
        uint4 v1 = feat8[(size_t)u1 * LPN + lane];
        uint4 v2 = feat8[(size_t)u2 * LPN + lane];
        uint4 v3 = feat8[(size_t)u3 * LPN + lane];
        d += (t0 + t1) + (t2 + t3);
        const __half2* p0 = (const __half2*)&v0;
        const __half2* p1 = (const __half2*)&v1;
        const __half2* p2 = (const __half2*)&v2;
        const __half2* p3 = (const __half2*)&v3;
#pragma unroll
        for (int k = 0; k < 4; k++) {
            float2 f0 = __half22float2(p0[k]);
            float2 f1 = __half22float2(p1[k]);
            float2 f2 = __half22float2(p2[k]);
            float2 f3 = __half22float2(p3[k]);
            acc[2*k]   = fmaf(t0, f0.x, acc[2*k]);
            acc[2*k+1] = fmaf(t0, f0.y, acc[2*k+1]);
            acc[2*k]   = fmaf(t1, f1.x, acc[2*k]);
            acc[2*k+1] = fmaf(t1, f1.y, acc[2*k+1]);
            acc[2*k]   = fmaf(t2, f2.x, acc[2*k]);
            acc[2*k+1] = fmaf(t2, f2.y, acc[2*k+1]);
            acc[2*k]   = fmaf(t3, f3.x, acc[2*k]);
            acc[2*k+1] = fmaf(t3, f3.y, acc[2*k+1]);
        }
    }
    for (; i < end; i++) {
        int u = __ldg(&csr[i]);
        float tv = __ldg(&t[(size_t)u * H + h]);
        uint4 v = feat8[(size_t)u * LPN + lane];
        const __half2* p = (const __half2*)&v;
        d += tv;
#pragma unroll
        for (int k = 0; k < 4; k++) {
            float2 f = __half22float2(p[k]);
            acc[2*k]   = fmaf(tv, f.x, acc[2*k]);
            acc[2*k+1] = fmaf(tv, f.y, acc[2*k+1]);
        }
    }

    float inv = d > 0.f ? __frcp_rn(d) : 0.f;
    float4 b0 = ((const float4*)bias)[lane * 2 + 0];
    float4 b1 = ((const float4*)bias)[lane * 2 + 1];
    float4 o0, o1;
    o0.x = fmaf(acc[0], inv, b0.x); o0.y = fmaf(acc[1], inv, b0.y);
    o0.z = fmaf(acc[2], inv, b0.z); o0.w = fmaf(acc[3], inv, b0.w);
    o1.x = fmaf(acc[4], inv, b1.x); o1.y = fmaf(acc[5], inv, b1.y);
    o1.z = fmaf(acc[6], inv, b1.z); o1.w = fmaf(acc[7], inv, b1.w);
    if (RELU) {
        o0.x = fmaxf(o0.x, 0.f); o0.y = fmaxf(o0.y, 0.f);
        o0.z = fmaxf(o0.z, 0.f); o0.w = fmaxf(o0.w, 0.f);
        o1.x = fmaxf(o1.x, 0.f); o1.y = fmaxf(o1.y, 0.f);
        o1.z = fmaxf(o1.z, 0.f); o1.w = fmaxf(o1.w, 0.f);
    }
    ((float4*)out)[(size_t)node * LPN * 2 + lane * 2 + 0] = o0;
    ((float4*)out)[(size_t)node * LPN * 2 + lane * 2 + 1] = o1;
}

// ---------------------------------------------------------------------------
extern "C" void kernel_launch(void* const* d_in, const int* in_sizes, int n_in,
                              void* d_out, int out_size) {
    const float* feat    = (const float*)d_in[0];
    const float* W0      = (const float*)d_in[1];
    const float* attn_l0 = (const float*)d_in[2];
    const float* bias0   = (const float*)d_in[3];
    const float* W1      = (const float*)d_in[4];
    const float* attn_l1 = (const float*)d_in[5];
    const float* bias1   = (const float*)d_in[6];
    const float* W2      = (const float*)d_in[7];
    const float* attn_l2 = (const float*)d_in[8];
    const float* bias2   = (const float*)d_in[9];
    const int*   src     = (const int*)d_in[10];
    const int*   dst     = (const int*)d_in[11];

    const int N = in_sizes[0] / 128;
    const int E = in_sizes[10];

    __half* p_feath;
    float *p_hid, *p_t;
    int *p_cnt, *p_ptr, *p_cur, *p_csr;
    cudaGetSymbolAddress((void**)&p_feath, g_feat_h);
    cudaGetSymbolAddress((void**)&p_hid,   g_hid);
    cudaGetSymbolAddress((void**)&p_t,     g_t);
    cudaGetSymbolAddress((void**)&p_cnt,   g_cnt);
    cudaGetSymbolAddress((void**)&p_ptr,   g_ptr);
    cudaGetSymbolAddress((void**)&p_cur,   g_cur);
    cudaGetSymbolAddress((void**)&p_csr,   g_csr);

    const int gGemm   = (N + 127) / 128;
    const int gEdge   = (E + 255) / 256;
    const int gNode16 = (N * 16 + 255) / 256;
    const int gNode8  = (N * 8 + 255) / 256;

    // -------- CSR build (shared by all layers) --------
    zero_cnt_kernel<<<(N + 1 + 255) / 256, 256>>>(p_cnt, N + 1);
    hist_kernel<<<gEdge, 256>>>(dst, p_cnt, E);
    scan_kernel<<<1, 1024>>>(p_cnt, p_ptr, p_cur, N);
    scatter_kernel<<<gEdge, 256>>>(src, dst, p_cur, p_csr, E);

    // -------- layer 0 --------
    gemm_kernel<128, 2><<<gGemm, 256>>>(feat, W0, attn_l0, p_feath, p_t, N);
    node_kernel<2, 64, true><<<gNode16, 256>>>(p_ptr, p_csr, p_feath, p_t, bias0, p_hid, N);

    // -------- layer 1 --------
    gemm_kernel<128, 2><<<gGemm, 256>>>(p_hid, W1, attn_l1, p_feath, p_t, N);
    node_kernel<2, 64, true><<<gNode16, 256>>>(p_ptr, p_csr, p_feath, p_t, bias1, p_hid, N);

    // -------- layer 2 (single head, no relu, write d_out) --------
    gemm_kernel<64, 1><<<gGemm, 128>>>(p_hid, W2, attn_l2, p_feath, p_t, N);
    node_kernel<1, 64, false><<<gNode8, 256>>>(p_ptr, p_csr, p_feath, p_t, bias2, (float*)d_out, N);
}

// round 6
// speedup vs baseline: 2.5808x; 1.1008x over previous
#include <cuda_runtime.h>
#include <cuda_fp16.h>
#include <cstdint>

// ---------------------------------------------------------------------------
// GAT 3-layer forward, gather-based (CSR by dst).
// R6: CSR build overlapped with GEMM0 on a side stream (event fork/join);
// hist/scatter unrolled x4 for atomic MLP. fp16 feat gather, fused score.
// ---------------------------------------------------------------------------

#define MAXN 50000
#define MAXE 800000
#define MAXW 128

__device__ __half g_feat_h[MAXN * MAXW];
__device__ float  g_hid [MAXN * MAXW];
__device__ float  g_t   [MAXN * 2];
__device__ int g_cnt[MAXN + 1];
__device__ int g_ptr[MAXN + 1];
__device__ int g_cur[MAXN + 1];
__device__ int g_csr[MAXE];

// ---------------- SGEMM + fused score epilogue ----------------
// C_h[N][BN] (fp16) = A[N][128] @ W[BN][128]^T ;  t[N][H] = exp(lrelu(C.attn))
template <int BN, int H>
__global__ void gemm_kernel(const float* __restrict__ A,
                            const float* __restrict__ W,
                            const float* __restrict__ attn,
                            __half* __restrict__ C_h,
                            float* __restrict__ t, int N) {
    constexpr int BM = 128, BK = 16, TM = 8, TN = 8, K = 128;
    constexpr int THREADS = (BM / TM) * (BN / TN);
    constexpr int KT = K / BK;
    constexpr int LA = BM * BK / 4 / THREADS;
    constexpr int LW = BN * BK / 4 / THREADS;
    constexpr int F = BN / H;

    __shared__ float As[2][BK * BM];
    __shared__ float Ws[2][BK * BN];
    __shared__ float sm_el[BM * H];

    const int tid  = threadIdx.x;
    const int tx   = tid % (BN / TN);
    const int ty   = tid / (BN / TN);
    const int row0 = blockIdx.x * BM;

    for (int i = tid; i < BM * H; i += THREADS) sm_el[i] = 0.f;

    const float4* A4 = (const float4*)A;
    const float4* W4 = (const float4*)W;

    float4 rA[LA], rW[LW];

    {
#pragma unroll
        for (int i = 0; i < LA; i++) {
            int f = tid + i * THREADS;
            int r = f >> 2, c4 = f & 3;
            rA[i] = (row0 + r < N) ? A4[(size_t)(row0 + r) * 32 + c4]
                                   : make_float4(0.f, 0.f, 0.f, 0.f);
        }
#pragma unroll
        for (int i = 0; i < LW; i++) {
            int f = tid + i * THREADS;
            int n = f >> 2, c4 = f & 3;
            rW[i] = W4[(size_t)n * 32 + c4];
        }
#pragma unroll
        for (int i = 0; i < LA; i++) {
            int f = tid + i * THREADS;
            int r = f >> 2, c4 = f & 3;
            As[0][(c4 * 4 + 0) * BM + r] = rA[i].x;
            As[0][(c4 * 4 + 1) * BM + r] = rA[i].y;
            As[0][(c4 * 4 + 2) * BM + r] = rA[i].z;
            As[0][(c4 * 4 + 3) * BM + r] = rA[i].w;
        }
#pragma unroll
        for (int i = 0; i < LW; i++) {
            int f = tid + i * THREADS;
            int n = f >> 2, c4 = f & 3;
            Ws[0][(c4 * 4 + 0) * BN + n] = rW[i].x;
            Ws[0][(c4 * 4 + 1) * BN + n] = rW[i].y;
            Ws[0][(c4 * 4 + 2) * BN + n] = rW[i].z;
            Ws[0][(c4 * 4 + 3) * BN + n] = rW[i].w;
        }
    }
    __syncthreads();

    float acc[TM][TN];
#pragma unroll
    for (int i = 0; i < TM; i++)
#pragma unroll
        for (int j = 0; j < TN; j++) acc[i][j] = 0.f;

    for (int kt = 0; kt < KT; kt++) {
        const int cur = kt & 1;
        if (kt + 1 < KT) {
#pragma unroll
            for (int i = 0; i < LA; i++) {
                int f = tid + i * THREADS;
                int r = f >> 2, c4 = f & 3;
                rA[i] = (row0 + r < N)
                        ? A4[(size_t)(row0 + r) * 32 + (kt + 1) * 4 + c4]
                        : make_float4(0.f, 0.f, 0.f, 0.f);
            }
#pragma unroll
            for (int i = 0; i < LW; i++) {
                int f = tid + i * THREADS;
                int n = f >> 2, c4 = f & 3;
                rW[i] = W4[(size_t)n * 32 + (kt + 1) * 4 + c4];
            }
        }
#pragma unroll
        for (int k = 0; k < BK; k++) {
            float4 a0 = *(const float4*)&As[cur][k * BM + ty * TM];
            float4 a1 = *(const float4*)&As[cur][k * BM + ty * TM + 4];
            float4 b0 = *(const float4*)&Ws[cur][k * BN + tx * TN];
            float4 b1 = *(const float4*)&Ws[cur][k * BN + tx * TN + 4];
            float av[TM] = {a0.x, a0.y, a0.z, a0.w, a1.x, a1.y, a1.z, a1.w};
            float bv[TN] = {b0.x, b0.y, b0.z, b0.w, b1.x, b1.y, b1.z, b1.w};
#pragma unroll
            for (int i = 0; i < TM; i++)
#pragma unroll
                for (int j = 0; j < TN; j++)
                    acc[i][j] = fmaf(av[i], bv[j], acc[i][j]);
        }
        if (kt + 1 < KT) {
            const int nxt = cur ^ 1;
            __syncthreads();
#pragma unroll
            for (int i = 0; i < LA; i++) {
                int f = tid + i * THREADS;
                int r = f >> 2, c4 = f & 3;
                As[nxt][(c4 * 4 + 0) * BM + r] = rA[i].x;
                As[nxt][(c4 * 4 + 1) * BM + r] = rA[i].y;
                As[nxt][(c4 * 4 + 2) * BM + r] = rA[i].z;
                As[nxt][(c4 * 4 + 3) * BM + r] = rA[i].w;
            }
#pragma unroll
            for (int i = 0; i < LW; i++) {
                int f = tid + i * THREADS;
                int n = f >> 2, c4 = f & 3;
                Ws[nxt][(c4 * 4 + 0) * BN + n] = rW[i].x;
                Ws[nxt][(c4 * 4 + 1) * BN + n] = rW[i].y;
                Ws[nxt][(c4 * 4 + 2) * BN + n] = rW[i].z;
                Ws[nxt][(c4 * 4 + 3) * BN + n] = rW[i].w;
            }
            __syncthreads();
        }
    }

    const int col0 = tx * TN;
    float av[TN];
#pragma unroll
    for (int j = 0; j < TN; j++) av[j] = attn[col0 + j];
    const int h = col0 / F;

#pragma unroll
    for (int i = 0; i < TM; i++) {
        int r   = ty * TM + i;
        int row = row0 + r;
        float part = 0.f;
#pragma unroll
        for (int j = 0; j < TN; j++) part += acc[i][j] * av[j];
        atomicAdd(&sm_el[r * H + h], part);
        if (row < N) {
            __half hv[TN];
#pragma unroll
            for (int j = 0; j < TN; j++) hv[j] = __float2half(acc[i][j]);
            *(uint4*)&C_h[(size_t)row * BN + col0] = *(uint4*)hv;
        }
    }
    __syncthreads();
    for (int i = tid; i < BM * H; i += THREADS) {
        int r = i / H, hh = i % H;
        int row = row0 + r;
        if (row < N) {
            float el = sm_el[i];
            float sv = el > 0.f ? el : 0.2f * el;
            t[(size_t)row * H + hh] = __expf(sv);
        }
    }
}

// ---------------- CSR build ----------------
__global__ void zero_cnt_kernel(int* __restrict__ cnt, int n) {
    int i = blockIdx.x * blockDim.x + threadIdx.x;
    if (i < n) cnt[i] = 0;
}

__global__ void hist_kernel(const int* __restrict__ dst, int* __restrict__ cnt, int E) {
    int i = (blockIdx.x * blockDim.x + threadIdx.x) * 4;
    if (i + 4 <= E) {
        int4 d = *(const int4*)&dst[i];
        atomicAdd(&cnt[d.x], 1);
        atomicAdd(&cnt[d.y], 1);
        atomicAdd(&cnt[d.z], 1);
        atomicAdd(&cnt[d.w], 1);
    } else {
        for (; i < E; i++) atomicAdd(&cnt[dst[i]], 1);
    }
}

__global__ void scan_kernel(const int* __restrict__ cnt, int* __restrict__ ptr,
                            int* __restrict__ cur, int N) {
    __shared__ int part[1024];
    const int tid = threadIdx.x;
    const int chunk = (N + 1023) / 1024;
    const int b = tid * chunk;
    int s = 0;
    for (int i = 0; i < chunk; i++)
        if (b + i < N) s += cnt[b + i];
    part[tid] = s;
    __syncthreads();
    for (int off = 1; off < 1024; off <<= 1) {
        int v = (tid >= off) ? part[tid - off] : 0;
        __syncthreads();
        part[tid] += v;
        __syncthreads();
    }
    int run = (tid > 0) ? part[tid - 1] : 0;
    for (int i = 0; i < chunk; i++) {
        if (b + i < N) {
            ptr[b + i] = run;
            cur[b + i] = run;
            run += cnt[b + i];
        }
    }
    if (tid == 1023) ptr[N] = part[1023];
}

__global__ void scatter_kernel(const int* __restrict__ src, const int* __restrict__ dst,
                               int* __restrict__ cur, int* __restrict__ csr, int E) {
    int i = (blockIdx.x * blockDim.x + threadIdx.x) * 4;
    if (i + 4 <= E) {
        int4 d = *(const int4*)&dst[i];
        int4 u = *(const int4*)&src[i];
        int p0 = atomicAdd(&cur[d.x], 1);
        int p1 = atomicAdd(&cur[d.y], 1);
        int p2 = atomicAdd(&cur[d.z], 1);
        int p3 = atomicAdd(&cur[d.w], 1);
        csr[p0] = u.x; csr[p1] = u.y; csr[p2] = u.z; csr[p3] = u.w;
    } else {
        for (; i < E; i++) {
            int p = atomicAdd(&cur[dst[i]], 1);
            csr[p] = src[i];
        }
    }
}

// ---------------- gather aggregation: LPN lanes per dst node ----------------
template <int H, int F, bool RELU>
__global__ void node_kernel(const int* __restrict__ ptr,
                            const int* __restrict__ csr,
                            const __half* __restrict__ feath,
                            const float* __restrict__ t,
                            const float* __restrict__ bias,
                            float* __restrict__ out, int N) {
    constexpr int LPN = H * F / 8;            // 16 (H=2) or 8 (H=1)
    int gid  = blockIdx.x * blockDim.x + threadIdx.x;
    int node = gid / LPN;
    int lane = gid % LPN;
    if (node >= N) return;
    const int beg = ptr[node];
    const int end = ptr[node + 1];
    const int h   = (H == 2) ? (lane >> 3) : 0;

    const uint4* feat8 = (const uint4*)feath;

    float acc[8];
#pragma unroll
    for (int k = 0; k < 8; k++) acc[k] = 0.f;
    float d = 0.f;

    int i = beg;
    for (; i + 4 <= end; i += 4) {
        int u0 = __ldg(&csr[i + 0]);
        int u1 = __ldg(&csr[i + 1]);
        int u2 = __ldg(&csr[i + 2]);
        int u3 = __ldg(&csr[i + 3]);
        float t0 = __ldg(&t[(size_t)u0 * H + h]);
        float t1 = __ldg(&t[(size_t)u1 * H + h]);
        float t2 = __ldg(&t[(size_t)u2 * H + h]);
        float t3 = __ldg(&t[(size_t)u3 * H + h]);
        uint4 v0 = feat8[(size_t)u0 * LPN + lane];
        uint4 v1 = feat8[(size_t)u1 * LPN + lane];
        uint4 v2 = feat8[(size_t)u2 * LPN + lane];
        uint4 v3 = feat8[(size_t)u3 * LPN + lane];
        d += (t0 + t1) + (t2 + t3);
        const __half2* p0 = (const __half2*)&v0;
        const __half2* p1 = (const __half2*)&v1;
        const __half2* p2 = (const __half2*)&v2;
        const __half2* p3 = (const __half2*)&v3;
#pragma unroll
        for (int k = 0; k < 4; k++) {
            float2 f0 = __half22float2(p0[k]);
            float2 f1 = __half22float2(p1[k]);
            float2 f2 = __half22float2(p2[k]);
            float2 f3 = __half22float2(p3[k]);
            acc[2*k]   = fmaf(t0, f0.x, acc[2*k]);
            acc[2*k+1] = fmaf(t0, f0.y, acc[2*k+1]);
            acc[2*k]   = fmaf(t1, f1.x, acc[2*k]);
            acc[2*k+1] = fmaf(t1, f1.y, acc[2*k+1]);
            acc[2*k]   = fmaf(t2, f2.x, acc[2*k]);
            acc[2*k+1] = fmaf(t2, f2.y, acc[2*k+1]);
            acc[2*k]   = fmaf(t3, f3.x, acc[2*k]);
            acc[2*k+1] = fmaf(t3, f3.y, acc[2*k+1]);
        }
    }
    for (; i < end; i++) {
        int u = __ldg(&csr[i]);
        float tv = __ldg(&t[(size_t)u * H + h]);
        uint4 v = feat8[(size_t)u * LPN + lane];
        const __half2* p = (const __half2*)&v;
        d += tv;
#pragma unroll
        for (int k = 0; k < 4; k++) {
            float2 f = __half22float2(p[k]);
            acc[2*k]   = fmaf(tv, f.x, acc[2*k]);
            acc[2*k+1] = fmaf(tv, f.y, acc[2*k+1]);
        }
    }

    float inv = d > 0.f ? __frcp_rn(d) : 0.f;
    float4 b0 = ((const float4*)bias)[lane * 2 + 0];
    float4 b1 = ((const float4*)bias)[lane * 2 + 1];
    float4 o0, o1;
    o0.x = fmaf(acc[0], inv, b0.x); o0.y = fmaf(acc[1], inv, b0.y);
    o0.z = fmaf(acc[2], inv, b0.z); o0.w = fmaf(acc[3], inv, b0.w);
    o1.x = fmaf(acc[4], inv, b1.x); o1.y = fmaf(acc[5], inv, b1.y);
    o1.z = fmaf(acc[6], inv, b1.z); o1.w = fmaf(acc[7], inv, b1.w);
    if (RELU) {
        o0.x = fmaxf(o0.x, 0.f); o0.y = fmaxf(o0.y, 0.f);
        o0.z = fmaxf(o0.z, 0.f); o0.w = fmaxf(o0.w, 0.f);
        o1.x = fmaxf(o1.x, 0.f); o1.y = fmaxf(o1.y, 0.f);
        o1.z = fmaxf(o1.z, 0.f); o1.w = fmaxf(o1.w, 0.f);
    }
    ((float4*)out)[(size_t)node * LPN * 2 + lane * 2 + 0] = o0;
    ((float4*)out)[(size_t)node * LPN * 2 + lane * 2 + 1] = o1;
}

// ---------------------------------------------------------------------------
static cudaStream_t s_side = nullptr;
static cudaEvent_t  ev_fork = nullptr, ev_join = nullptr;

extern "C" void kernel_launch(void* const* d_in, const int* in_sizes, int n_in,
                              void* d_out, int out_size) {
    const float* feat    = (const float*)d_in[0];
    const float* W0      = (const float*)d_in[1];
    const float* attn_l0 = (const float*)d_in[2];
    const float* bias0   = (const float*)d_in[3];
    const float* W1      = (const float*)d_in[4];
    const float* attn_l1 = (const float*)d_in[5];
    const float* bias1   = (const float*)d_in[6];
    const float* W2      = (const float*)d_in[7];
    const float* attn_l2 = (const float*)d_in[8];
    const float* bias2   = (const float*)d_in[9];
    const int*   src     = (const int*)d_in[10];
    const int*   dst     = (const int*)d_in[11];

    const int N = in_sizes[0] / 128;
    const int E = in_sizes[10];

    __half* p_feath;
    float *p_hid, *p_t;
    int *p_cnt, *p_ptr, *p_cur, *p_csr;
    cudaGetSymbolAddress((void**)&p_feath, g_feat_h);
    cudaGetSymbolAddress((void**)&p_hid,   g_hid);
    cudaGetSymbolAddress((void**)&p_t,     g_t);
    cudaGetSymbolAddress((void**)&p_cnt,   g_cnt);
    cudaGetSymbolAddress((void**)&p_ptr,   g_ptr);
    cudaGetSymbolAddress((void**)&p_cur,   g_cur);
    cudaGetSymbolAddress((void**)&p_csr,   g_csr);

    // lazy one-time infra init (first call is the uncaptured correctness run)
    if (s_side == nullptr) {
        cudaStreamCreateWithFlags(&s_side, cudaStreamNonBlocking);
        cudaEventCreateWithFlags(&ev_fork, cudaEventDisableTiming);
        cudaEventCreateWithFlags(&ev_join, cudaEventDisableTiming);
    }

    const int gGemm   = (N + 127) / 128;
    const int gEdge4  = (E / 4 + 255) / 256 + 1;
    const int gNode16 = (N * 16 + 255) / 256;
    const int gNode8  = (N * 8 + 255) / 256;

    // -------- fork: CSR build on side stream, GEMM0 on main --------
    cudaEventRecord(ev_fork, 0);
    cudaStreamWaitEvent(s_side, ev_fork, 0);

    zero_cnt_kernel<<<(N + 1 + 255) / 256, 256, 0, s_side>>>(p_cnt, N + 1);
    hist_kernel<<<gEdge4, 256, 0, s_side>>>(dst, p_cnt, E);
    scan_kernel<<<1, 1024, 0, s_side>>>(p_cnt, p_ptr, p_cur, N);
    scatter_kernel<<<gEdge4, 256, 0, s_side>>>(src, dst, p_cur, p_csr, E);
    cudaEventRecord(ev_join, s_side);

    gemm_kernel<128, 2><<<gGemm, 256>>>(feat, W0, attn_l0, p_feath, p_t, N);

    // -------- join, then remaining (serial) pipeline --------
    cudaStreamWaitEvent(0, ev_join, 0);

    node_kernel<2, 64, true><<<gNode16, 256>>>(p_ptr, p_csr, p_feath, p_t, bias0, p_hid, N);

    gemm_kernel<128, 2><<<gGemm, 256>>>(p_hid, W1, attn_l1, p_feath, p_t, N);
    node_kernel<2, 64, true><<<gNode16, 256>>>(p_ptr, p_csr, p_feath, p_t, bias1, p_hid, N);

    gemm_kernel<64, 1><<<gGemm, 128>>>(p_hid, W2, attn_l2, p_feath, p_t, N);
    node_kernel<1, 64, false><<<gNode8, 256>>>(p_ptr, p_csr, p_feath, p_t, bias2, (float*)d_out, N);
}

// round 7
// speedup vs baseline: 2.7740x; 1.0749x over previous
#include <cuda_runtime.h>
#include <cuda_fp16.h>
#include <cstdint>

// ---------------------------------------------------------------------------
// GAT 3-layer forward, gather-based (CSR by dst).
// R7: GEMM on tensor pipe via mma.sync m16n8k16 fp16 with 2-term error-
// compensated split (hi/lo), 3 mma passes -> fp32-level accuracy.
// Fused score epilogue + fp16 feat store kept. CSR build overlapped w/ GEMM0.
// ---------------------------------------------------------------------------

#define MAXN 50000
#define MAXE 800000
#define MAXW 128

__device__ __half g_feat_h[MAXN * MAXW];
__device__ float  g_hid [MAXN * MAXW];
__device__ float  g_t   [MAXN * 2];
__device__ int g_cnt[MAXN + 1];
__device__ int g_ptr[MAXN + 1];
__device__ int g_cur[MAXN + 1];
__device__ int g_csr[MAXE];

__device__ __forceinline__ void mma16816(float* d, const uint32_t* a, const uint32_t* b) {
    asm volatile(
        "mma.sync.aligned.m16n8k16.row.col.f32.f16.f16.f32 "
        "{%0,%1,%2,%3}, {%4,%5,%6,%7}, {%8,%9}, {%0,%1,%2,%3};\n"
        : "+f"(d[0]), "+f"(d[1]), "+f"(d[2]), "+f"(d[3])
        : "r"(a[0]), "r"(a[1]), "r"(a[2]), "r"(a[3]), "r"(b[0]), "r"(b[1]));
}

// ---------------- tensor-core GEMM + fused score epilogue ----------------
// C_h[N][BN] (fp16) = A[N][128] @ W[BN][128]^T ;  t[N][H] = exp(lrelu(C.attn))
// A, W split into fp16 hi/lo planes in smem; D = Ahi*Bhi + Ahi*Blo + Alo*Bhi.
template <int BN, int H>
__global__ void __launch_bounds__(256, 1)
gemm_tc_kernel(const float* __restrict__ A,
               const float* __restrict__ W,
               const float* __restrict__ attn,
               __half* __restrict__ C_h,
               float* __restrict__ t, int N) {
    constexpr int BM = 128, K = 128;
    constexpr int SK = K + 8;          // half stride (136): conflict-free frags
    constexpr int WN = BN / 4;         // warp n-width (32 or 16)
    constexpr int MT = 4;              // m16 tiles per warp (warp M = 64)
    constexpr int NT = WN / 8;         // n8 tiles per warp (4 or 2)
    constexpr int F  = BN / H;

    extern __shared__ __half sm[];
    __half* sAhi = sm;                    // [BM][SK]
    __half* sAlo = sAhi + BM * SK;
    __half* sWhi = sAlo + BM * SK;        // [BN][SK]
    __half* sWlo = sWhi + BN * SK;
    float*  sm_el = (float*)(sWlo + BN * SK);   // [BM*H]

    const int tid  = threadIdx.x;
    const int warp = tid >> 5;
    const int lane = tid & 31;
    const int row0 = blockIdx.x * BM;
    const int m0w  = (warp >> 2) * 64;
    const int n0w  = (warp & 3) * WN;
    const int fr   = lane >> 2;        // 0..7
    const int fc   = lane & 3;         // 0..3

    for (int i = tid; i < BM * H; i += 256) sm_el[i] = 0.f;

    // ---- stage A (fp32 -> hi/lo halves) ----
    const float4* A4 = (const float4*)A;
    for (int f = tid; f < BM * 32; f += 256) {
        int r = f >> 5, c4 = f & 31;
        float4 v = make_float4(0.f, 0.f, 0.f, 0.f);
        if (row0 + r < N) v = A4[(size_t)(row0 + r) * 32 + c4];
        float vv[4] = {v.x, v.y, v.z, v.w};
        __half hi[4], lo[4];
#pragma unroll
        for (int j = 0; j < 4; j++) {
            hi[j] = __float2half(vv[j]);
            lo[j] = __float2half(vv[j] - __half2float(hi[j]));
        }
        int off = r * SK + c4 * 4;
        *(uint2*)&sAhi[off] = *(uint2*)hi;
        *(uint2*)&sAlo[off] = *(uint2*)lo;
    }
    // ---- stage W ----
    const float4* W4 = (const float4*)W;
    for (int f = tid; f < BN * 32; f += 256) {
        int n = f >> 5, c4 = f & 31;
        float4 v = W4[(size_t)n * 32 + c4];
        float vv[4] = {v.x, v.y, v.z, v.w};
        __half hi[4], lo[4];
#pragma unroll
        for (int j = 0; j < 4; j++) {
            hi[j] = __float2half(vv[j]);
            lo[j] = __float2half(vv[j] - __half2float(hi[j]));
        }
        int off = n * SK + c4 * 4;
        *(uint2*)&sWhi[off] = *(uint2*)hi;
        *(uint2*)&sWlo[off] = *(uint2*)lo;
    }
    __syncthreads();

    float acc[MT][NT][4];
#pragma unroll
    for (int mt = 0; mt < MT; mt++)
#pragma unroll
        for (int nt = 0; nt < NT; nt++)
#pragma unroll
            for (int j = 0; j < 4; j++) acc[mt][nt][j] = 0.f;

#pragma unroll
    for (int kt = 0; kt < 8; kt++) {
        const int k0 = kt * 16;
        uint32_t ahi[MT][4], alo[MT][4];
#pragma unroll
        for (int mt = 0; mt < MT; mt++) {
            const __half* pa = &sAhi[(m0w + mt * 16 + fr) * SK + k0 + fc * 2];
            const __half* pl = &sAlo[(m0w + mt * 16 + fr) * SK + k0 + fc * 2];
            ahi[mt][0] = *(const uint32_t*)pa;
            ahi[mt][1] = *(const uint32_t*)(pa + 8 * SK);
            ahi[mt][2] = *(const uint32_t*)(pa + 8);
            ahi[mt][3] = *(const uint32_t*)(pa + 8 * SK + 8);
            alo[mt][0] = *(const uint32_t*)pl;
            alo[mt][1] = *(const uint32_t*)(pl + 8 * SK);
            alo[mt][2] = *(const uint32_t*)(pl + 8);
            alo[mt][3] = *(const uint32_t*)(pl + 8 * SK + 8);
        }
        uint32_t bhi[NT][2], blo[NT][2];
#pragma unroll
        for (int nt = 0; nt < NT; nt++) {
            const __half* pb = &sWhi[(n0w + nt * 8 + fr) * SK + k0 + fc * 2];
            const __half* pl = &sWlo[(n0w + nt * 8 + fr) * SK + k0 + fc * 2];
            bhi[nt][0] = *(const uint32_t*)pb;
            bhi[nt][1] = *(const uint32_t*)(pb + 8);
            blo[nt][0] = *(const uint32_t*)pl;
            blo[nt][1] = *(const uint32_t*)(pl + 8);
        }
#pragma unroll
        for (int mt = 0; mt < MT; mt++)
#pragma unroll
            for (int nt = 0; nt < NT; nt++) {
                mma16816(acc[mt][nt], ahi[mt], bhi[nt]);
                mma16816(acc[mt][nt], ahi[mt], blo[nt]);
                mma16816(acc[mt][nt], alo[mt], bhi[nt]);
            }
    }

    // ---- epilogue: fused score partials + fp16 store ----
    const int hh = n0w / F;
    float av0[NT], av1[NT];
#pragma unroll
    for (int nt = 0; nt < NT; nt++) {
        int col = n0w + nt * 8 + fc * 2;
        av0[nt] = attn[col];
        av1[nt] = attn[col + 1];
    }
#pragma unroll
    for (int mt = 0; mt < MT; mt++) {
        int rb0 = m0w + mt * 16 + fr;
        int rb1 = rb0 + 8;
        float p0 = 0.f, p1 = 0.f;
#pragma unroll
        for (int nt = 0; nt < NT; nt++) {
            p0 += acc[mt][nt][0] * av0[nt] + acc[mt][nt][1] * av1[nt];
            p1 += acc[mt][nt][2] * av0[nt] + acc[mt][nt][3] * av1[nt];
        }
        atomicAdd(&sm_el[rb0 * H + hh], p0);
        atomicAdd(&sm_el[rb1 * H + hh], p1);
        int g0 = row0 + rb0, g1 = row0 + rb1;
        if (g0 < N) {
#pragma unroll
            for (int nt = 0; nt < NT; nt++) {
                int col = n0w + nt * 8 + fc * 2;
                __half2 hv = __halves2half2(__float2half(acc[mt][nt][0]),
                                            __float2half(acc[mt][nt][1]));
                *(__half2*)&C_h[(size_t)g0 * BN + col] = hv;
            }
        }
        if (g1 < N) {
#pragma unroll
            for (int nt = 0; nt < NT; nt++) {
                int col = n0w + nt * 8 + fc * 2;
                __half2 hv = __halves2half2(__float2half(acc[mt][nt][2]),
                                            __float2half(acc[mt][nt][3]));
                *(__half2*)&C_h[(size_t)g1 * BN + col] = hv;
            }
        }
    }
    __syncthreads();
    for (int i = tid; i < BM * H; i += 256) {
        int r = i / H, h2 = i % H;
        int row = row0 + r;
        if (row < N) {
            float el = sm_el[i];
            float sv = el > 0.f ? el : 0.2f * el;
            t[(size_t)row * H + h2] = __expf(sv);
        }
    }
}

// ---------------- CSR build ----------------
__global__ void zero_cnt_kernel(int* __restrict__ cnt, int n) {
    int i = blockIdx.x * blockDim.x + threadIdx.x;
    if (i < n) cnt[i] = 0;
}

__global__ void hist_kernel(const int* __restrict__ dst, int* __restrict__ cnt, int E) {
    int i = (blockIdx.x * blockDim.x + threadIdx.x) * 4;
    if (i + 4 <= E) {
        int4 d = *(const int4*)&dst[i];
        atomicAdd(&cnt[d.x], 1);
        atomicAdd(&cnt[d.y], 1);
        atomicAdd(&cnt[d.z], 1);
        atomicAdd(&cnt[d.w], 1);
    } else {
        for (; i < E; i++) atomicAdd(&cnt[dst[i]], 1);
    }
}

__global__ void scan_kernel(const int* __restrict__ cnt, int* __restrict__ ptr,
                            int* __restrict__ cur, int N) {
    __shared__ int part[1024];
    const int tid = threadIdx.x;
    const int chunk = (N + 1023) / 1024;
    const int b = tid * chunk;
    int s = 0;
    for (int i = 0; i < chunk; i++)
        if (b + i < N) s += cnt[b + i];
    part[tid] = s;
    __syncthreads();
    for (int off = 1; off < 1024; off <<= 1) {
        int v = (tid >= off) ? part[tid - off] : 0;
        __syncthreads();
        part[tid] += v;
        __syncthreads();
    }
    int run = (tid > 0) ? part[tid - 1] : 0;
    for (int i = 0; i < chunk; i++) {
        if (b + i < N) {
            ptr[b + i] = run;
            cur[b + i] = run;
            run += cnt[b + i];
        }
    }
    if (tid == 1023) ptr[N] = part[1023];
}

__global__ void scatter_kernel(const int* __restrict__ src, const int* __restrict__ dst,
                               int* __restrict__ cur, int* __restrict__ csr, int E) {
    int i = (blockIdx.x * blockDim.x + threadIdx.x) * 4;
    if (i + 4 <= E) {
        int4 d = *(const int4*)&dst[i];
        int4 u = *(const int4*)&src[i];
        int p0 = atomicAdd(&cur[d.x], 1);
        int p1 = atomicAdd(&cur[d.y], 1);
        int p2 = atomicAdd(&cur[d.z], 1);
        int p3 = atomicAdd(&cur[d.w], 1);
        csr[p0] = u.x; csr[p1] = u.y; csr[p2] = u.z; csr[p3] = u.w;
    } else {
        for (; i < E; i++) {
            int p = atomicAdd(&cur[dst[i]], 1);
            csr[p] = src[i];
        }
    }
}

// ---------------- gather aggregation: LPN lanes per dst node ----------------
template <int H, int F, bool RELU>
__global__ void node_kernel(const int* __restrict__ ptr,
                            const int* __restrict__ csr,
                            const __half* __restrict__ feath,
                            const float* __restrict__ t,
                            const float* __restrict__ bias,
                            float* __restrict__ out, int N) {
    constexpr int LPN = H * F / 8;            // 16 (H=2) or 8 (H=1)
    int gid  = blockIdx.x * blockDim.x + threadIdx.x;
    int node = gid / LPN;
    int lane = gid % LPN;
    if (node >= N) return;
    const int beg = ptr[node];
    const int end = ptr[node + 1];
    const int h   = (H == 2) ? (lane >> 3) : 0;

    const uint4* feat8 = (const uint4*)feath;

    float acc[8];
#pragma unroll
    for (int k = 0; k < 8; k++) acc[k] = 0.f;
    float d = 0.f;

    int i = beg;
    for (; i + 4 <= end; i += 4) {
        int u0 = __ldg(&csr[i + 0]);
        int u1 = __ldg(&csr[i + 1]);
        int u2 = __ldg(&csr[i + 2]);
        int u3 = __ldg(&csr[i + 3]);
        float t0 = __ldg(&t[(size_t)u0 * H + h]);
        float t1 = __ldg(&t[(size_t)u1 * H + h]);
        float t2 = __ldg(&t[(size_t)u2 * H + h]);
        float t3 = __ldg(&t[(size_t)u3 * H + h]);
        uint4 v0 = feat8[(size_t)u0 * LPN + lane];
        uint4 v1 = feat8[(size_t)u1 * LPN + lane];
        uint4 v2 = feat8[(size_t)u2 * LPN + lane];
        uint4 v3 = feat8[(size_t)u3 * LPN + lane];
        d += (t0 + t1) + (t2 + t3);
        const __half2* p0 = (const __half2*)&v0;
        const __half2* p1 = (const __half2*)&v1;
        const __half2* p2 = (const __half2*)&v2;
        const __half2* p3 = (const __half2*)&v3;
#pragma unroll
        for (int k = 0; k < 4; k++) {
            float2 f0 = __half22float2(p0[k]);
            float2 f1 = __half22float2(p1[k]);
            float2 f2 = __half22float2(p2[k]);
            float2 f3 = __half22float2(p3[k]);
            acc[2*k]   = fmaf(t0, f0.x, acc[2*k]);
            acc[2*k+1] = fmaf(t0, f0.y, acc[2*k+1]);
            acc[2*k]   = fmaf(t1, f1.x, acc[2*k]);
            acc[2*k+1] = fmaf(t1, f1.y, acc[2*k+1]);
            acc[2*k]   = fmaf(t2, f2.x, acc[2*k]);
            acc[2*k+1] = fmaf(t2, f2.y, acc[2*k+1]);
            acc[2*k]   = fmaf(t3, f3.x, acc[2*k]);
            acc[2*k+1] = fmaf(t3, f3.y, acc[2*k+1]);
        }
    }
    for (; i < end; i++) {
        int u = __ldg(&csr[i]);
        float tv = __ldg(&t[(size_t)u * H + h]);
        uint4 v = feat8[(size_t)u * LPN + lane];
        const __half2* p = (const __half2*)&v;
        d += tv;
#pragma unroll
        for (int k = 0; k < 4; k++) {
            float2 f = __half22float2(p[k]);
            acc[2*k]   = fmaf(tv, f.x, acc[2*k]);
            acc[2*k+1] = fmaf(tv, f.y, acc[2*k+1]);
        }
    }

    float inv = d > 0.f ? __frcp_rn(d) : 0.f;
    float4 b0 = ((const float4*)bias)[lane * 2 + 0];
    float4 b1 = ((const float4*)bias)[lane * 2 + 1];
    float4 o0, o1;
    o0.x = fmaf(acc[0], inv, b0.x); o0.y = fmaf(acc[1], inv, b0.y);
    o0.z = fmaf(acc[2], inv, b0.z); o0.w = fmaf(acc[3], inv, b0.w);
    o1.x = fmaf(acc[4], inv, b1.x); o1.y = fmaf(acc[5], inv, b1.y);
    o1.z = fmaf(acc[6], inv, b1.z); o1.w = fmaf(acc[7], inv, b1.w);
    if (RELU) {
        o0.x = fmaxf(o0.x, 0.f); o0.y = fmaxf(o0.y, 0.f);
        o0.z = fmaxf(o0.z, 0.f); o0.w = fmaxf(o0.w, 0.f);
        o1.x = fmaxf(o1.x, 0.f); o1.y = fmaxf(o1.y, 0.f);
        o1.z = fmaxf(o1.z, 0.f); o1.w = fmaxf(o1.w, 0.f);
    }
    ((float4*)out)[(size_t)node * LPN * 2 + lane * 2 + 0] = o0;
    ((float4*)out)[(size_t)node * LPN * 2 + lane * 2 + 1] = o1;
}

// ---------------------------------------------------------------------------
static cudaStream_t s_side = nullptr;
static cudaEvent_t  ev_fork = nullptr, ev_join = nullptr;

extern "C" void kernel_launch(void* const* d_in, const int* in_sizes, int n_in,
                              void* d_out, int out_size) {
    const float* feat    = (const float*)d_in[0];
    const float* W0      = (const float*)d_in[1];
    const float* attn_l0 = (const float*)d_in[2];
    const float* bias0   = (const float*)d_in[3];
    const float* W1      = (const float*)d_in[4];
    const float* attn_l1 = (const float*)d_in[5];
    const float* bias1   = (const float*)d_in[6];
    const float* W2      = (const float*)d_in[7];
    const float* attn_l2 = (const float*)d_in[8];
    const float* bias2   = (const float*)d_in[9];
    const int*   src     = (const int*)d_in[10];
    const int*   dst     = (const int*)d_in[11];

    const int N = in_sizes[0] / 128;
    const int E = in_sizes[10];

    __half* p_feath;
    float *p_hid, *p_t;
    int *p_cnt, *p_ptr, *p_cur, *p_csr;
    cudaGetSymbolAddress((void**)&p_feath, g_feat_h);
    cudaGetSymbolAddress((void**)&p_hid,   g_hid);
    cudaGetSymbolAddress((void**)&p_t,     g_t);
    cudaGetSymbolAddress((void**)&p_cnt,   g_cnt);
    cudaGetSymbolAddress((void**)&p_ptr,   g_ptr);
    cudaGetSymbolAddress((void**)&p_cur,   g_cur);
    cudaGetSymbolAddress((void**)&p_csr,   g_csr);

    // lazy one-time infra init (first call is the uncaptured correctness run)
    if (s_side == nullptr) {
        cudaStreamCreateWithFlags(&s_side, cudaStreamNonBlocking);
        cudaEventCreateWithFlags(&ev_fork, cudaEventDisableTiming);
        cudaEventCreateWithFlags(&ev_join, cudaEventDisableTiming);
    }

    constexpr int SK = 128 + 8;
    const int SMEM128 = (2 * 128 + 2 * 128) * SK * 2 + 128 * 2 * 4;
    const int SMEM64  = (2 * 128 + 2 * 64)  * SK * 2 + 128 * 1 * 4;
    cudaFuncSetAttribute(gemm_tc_kernel<128, 2>,
                         cudaFuncAttributeMaxDynamicSharedMemorySize, SMEM128);
    cudaFuncSetAttribute(gemm_tc_kernel<64, 1>,
                         cudaFuncAttributeMaxDynamicSharedMemorySize, SMEM64);

    const int gGemm   = (N + 127) / 128;
    const int gEdge4  = (E / 4 + 255) / 256 + 1;
    const int gNode16 = (N * 16 + 255) / 256;
    const int gNode8  = (N * 8 + 255) / 256;

    // -------- fork: CSR build on side stream, GEMM0 on main --------
    cudaEventRecord(ev_fork, 0);
    cudaStreamWaitEvent(s_side, ev_fork, 0);

    zero_cnt_kernel<<<(N + 1 + 255) / 256, 256, 0, s_side>>>(p_cnt, N + 1);
    hist_kernel<<<gEdge4, 256, 0, s_side>>>(dst, p_cnt, E);
    scan_kernel<<<1, 1024, 0, s_side>>>(p_cnt, p_ptr, p_cur, N);
    scatter_kernel<<<gEdge4, 256, 0, s_side>>>(src, dst, p_cur, p_csr, E);
    cudaEventRecord(ev_join, s_side);

    gemm_tc_kernel<128, 2><<<gGemm, 256, SMEM128>>>(feat, W0, attn_l0, p_feath, p_t, N);

    // -------- join, then remaining (serial) pipeline --------
    cudaStreamWaitEvent(0, ev_join, 0);

    node_kernel<2, 64, true><<<gNode16, 256>>>(p_ptr, p_csr, p_feath, p_t, bias0, p_hid, N);

    gemm_tc_kernel<128, 2><<<gGemm, 256, SMEM128>>>(p_hid, W1, attn_l1, p_feath, p_t, N);
    node_kernel<2, 64, true><<<gNode16, 256>>>(p_ptr, p_csr, p_feath, p_t, bias1, p_hid, N);

    gemm_tc_kernel<64, 1><<<gGemm, 256, SMEM64>>>(p_hid, W2, attn_l2, p_feath, p_t, N);
    node_kernel<1, 64, false><<<gNode8, 256>>>(p_ptr, p_csr, p_feath, p_t, bias2, (float*)d_out, N);
}